// round 1
// baseline (speedup 1.0000x reference)
#include <cuda_runtime.h>
#include <cuda_bf16.h>
#include <mma.h>

using namespace nvcuda;

#define B_SZ   16384
#define DIN    2048
#define Z_OFF  0
#define XHAT_OFF (16384L*3)
#define SCAL_OFF (16384L*3 + 16384L*2048)

// ---------------- scratch (device globals; no allocation allowed) ----------------
__device__ float g_prea[B_SZ*128];   // x-path pre-activation (no bias, no treatment col)
__device__ float g_pred[B_SZ*128];   // x_dot-path
__device__ float g_h3 [B_SZ*128];
__device__ float g_dzd3[B_SZ*128];
__device__ float g_part_po[512], g_part_tr[512], g_part_sz[512];
__device__ float g_part_rec[2048], g_part_sx[2048];

// ================= K1: big GEMM  (M=16384, N=128, K=2048) tf32x3 =================
// out[m][n] = sum_k A[m][k] * eW1[n][k]   (A = x or x_dot by blockIdx.y)
__global__ void __launch_bounds__(256) k1_gemm(
    const float* __restrict__ x, const float* __restrict__ x_dot,
    const float* __restrict__ eW1)
{
    __shared__ float As[128*36];
    __shared__ float Bs[128*36];
    const int path = blockIdx.y;
    const float* A = (path == 0) ? x : x_dot;
    float* Out = (path == 0) ? g_prea : g_pred;
    const int m0 = blockIdx.x * 128;
    const int tid = threadIdx.x;
    const int w  = tid >> 5;
    const int wr = w >> 2;     // 0..1 (64-row half)
    const int wc = w & 3;      // 0..3 (32-col quarter)

    wmma::fragment<wmma::accumulator,16,16,8,float> acc[4][2];
    #pragma unroll
    for (int i=0;i<4;i++)
        #pragma unroll
        for(int j=0;j<2;j++) wmma::fill_fragment(acc[i][j], 0.0f);

    for (int k0 = 0; k0 < 2048; k0 += 32) {
        // A tile 128x32, float4
        {
            const float4* src = reinterpret_cast<const float4*>(A);
            #pragma unroll
            for (int i = 0; i < 4; i++) {
                int p  = tid + 256*i;      // 0..1023
                int r  = p >> 3;
                int c4 = p & 7;
                float4 v = src[(long)(m0 + r) * 512 + (k0 >> 2) + c4];
                *reinterpret_cast<float4*>(&As[r*36 + c4*4]) = v;
            }
        }
        // B tile: eW1[n][k0..k0+31], row stride 2049 (odd -> scalar loads)
        {
            #pragma unroll
            for (int i = 0; i < 16; i++) {
                int p  = tid + 256*i;      // 0..4095
                int n  = p >> 5;
                int kk = p & 31;
                Bs[n*36 + kk] = eW1[n*2049 + k0 + kk];
            }
        }
        __syncthreads();
        #pragma unroll
        for (int kk = 0; kk < 32; kk += 8) {
            wmma::fragment<wmma::matrix_b,16,16,8,wmma::precision::tf32,wmma::col_major> bh[2], bl[2];
            #pragma unroll
            for (int j=0;j<2;j++) {
                wmma::fragment<wmma::matrix_b,16,16,8,wmma::precision::tf32,wmma::col_major> braw;
                wmma::load_matrix_sync(braw, &Bs[(wc*32 + j*16)*36 + kk], 36);
                #pragma unroll
                for (int e=0;e<braw.num_elements;e++) {
                    float v  = braw.x[e];
                    float hi = wmma::__float_to_tf32(v);
                    bh[j].x[e] = hi;
                    bl[j].x[e] = wmma::__float_to_tf32(v - hi);
                }
            }
            #pragma unroll
            for (int i=0;i<4;i++) {
                wmma::fragment<wmma::matrix_a,16,16,8,wmma::precision::tf32,wmma::row_major> araw, ah, al;
                wmma::load_matrix_sync(araw, &As[(wr*64 + i*16)*36 + kk], 36);
                #pragma unroll
                for (int e=0;e<araw.num_elements;e++) {
                    float v  = araw.x[e];
                    float hi = wmma::__float_to_tf32(v);
                    ah.x[e] = hi;
                    al.x[e] = wmma::__float_to_tf32(v - hi);
                }
                #pragma unroll
                for (int j=0;j<2;j++) {
                    wmma::mma_sync(acc[i][j], ah, bh[j], acc[i][j]);
                    wmma::mma_sync(acc[i][j], al, bh[j], acc[i][j]);
                    wmma::mma_sync(acc[i][j], ah, bl[j], acc[i][j]);
                }
            }
        }
        __syncthreads();
    }
    #pragma unroll
    for (int i=0;i<4;i++)
        #pragma unroll
        for (int j=0;j<2;j++) {
            float* p = Out + (long)(m0 + wr*64 + i*16)*128 + wc*32 + j*16;
            wmma::store_matrix_sync(p, acc[i][j], 128, wmma::mem_row_major);
        }
}

// ================= K2: fused middle chain (warp-per-row) =================
// smem layout (floats), weights stored TRANSPOSED for conflict-free access
#define W2T_OFF   0                         // 128*64
#define W3T_OFF   (W2T_OFF + 128*64)        // 64*32
#define W4S_OFF   (W3T_OFF + 64*32)         // 3*32
#define DW1T_OFF  (W4S_OFF + 96)            // 3*32
#define DW2T_OFF  (DW1T_OFF + 96)           // 32*64
#define DW3T_OFF  (DW2T_OFF + 32*64)        // 64*128
#define EB1_OFF   (DW3T_OFF + 64*128)
#define EB2_OFF   (EB1_OFF + 128)
#define EB3_OFF   (EB2_OFF + 64)
#define EB4_OFF   (EB3_OFF + 32)
#define DB1_OFF   (EB4_OFF + 4)
#define DB2_OFF   (DB1_OFF + 32)
#define DB3_OFF   (DB2_OFF + 64)
#define W1L_OFF   (DB3_OFF + 128)
#define COEF_OFF  (W1L_OFF + 128)
#define BUF_OFF   (COEF_OFF + 24)           // 8 warps * 256
#define LRED_OFF  (BUF_OFF + 8*256)         // 24
#define K2_FLOATS (LRED_OFF + 24)
#define K2_SMEM   (K2_FLOATS * 4)

__device__ __forceinline__ float sigf(float x) { return 1.f/(1.f+__expf(-x)); }

__global__ void __launch_bounds__(256) k2_chain(
    const float* __restrict__ treatment, const float* __restrict__ size_,
    const float* __restrict__ eW1, const float* __restrict__ eb1,
    const float* __restrict__ eW2, const float* __restrict__ eb2,
    const float* __restrict__ eW3, const float* __restrict__ eb3,
    const float* __restrict__ eW4, const float* __restrict__ eb4,
    const float* __restrict__ dW1, const float* __restrict__ db1,
    const float* __restrict__ dW2, const float* __restrict__ db2,
    const float* __restrict__ dW3, const float* __restrict__ db3,
    const float* __restrict__ coef,
    float* __restrict__ out)
{
    extern __shared__ float sm[];
    const int tid = threadIdx.x;

    // ---- cooperative weight staging (transposed) ----
    for (int i = tid; i < 64*128; i += 256) { int n=i>>7, k=i&127; sm[W2T_OFF + k*64 + n] = eW2[i]; }
    for (int i = tid; i < 32*64;  i += 256) { int n=i>>6, k=i&63;  sm[W3T_OFF + k*32 + n] = eW3[i]; }
    for (int i = tid; i < 3*32;   i += 256) sm[W4S_OFF + i] = eW4[i];                 // [j][k]
    for (int i = tid; i < 32*3;   i += 256) { int n=i/3,  k=i%3;  sm[DW1T_OFF + k*32 + n] = dW1[i]; }
    for (int i = tid; i < 64*32;  i += 256) { int n=i>>5, k=i&31; sm[DW2T_OFF + k*64 + n] = dW2[i]; }
    for (int i = tid; i < 128*64; i += 256) { int n=i>>6, k=i&63; sm[DW3T_OFF + k*128 + n] = dW3[i]; }
    if (tid < 128) sm[EB1_OFF+tid] = eb1[tid];
    if (tid < 64)  sm[EB2_OFF+tid] = eb2[tid];
    if (tid < 32)  sm[EB3_OFF+tid] = eb3[tid];
    if (tid < 3)   sm[EB4_OFF+tid] = eb4[tid];
    if (tid < 32)  sm[DB1_OFF+tid] = db1[tid];
    if (tid < 64)  sm[DB2_OFF+tid] = db2[tid];
    if (tid < 128) sm[DB3_OFF+tid] = db3[tid];
    if (tid < 128) sm[W1L_OFF+tid] = eW1[tid*2049 + 2048];
    if (tid < 21)  sm[COEF_OFF+tid] = coef[tid];
    __syncthreads();

    const int w = tid >> 5, lane = tid & 31;
    float* abuf = sm + BUF_OFF + w*256;
    float* dbuf = abuf + 128;
    float po = 0.f, tr = 0.f, szl = 0.f;

    for (int rr = 0; rr < 4; rr++) {
        const int row = (blockIdx.x*8 + w)*4 + rr;
        const float tre = treatment[row];

        // encoder layer1 (post-GEMM): bias + treatment col + sigmoid; derivative input
        #pragma unroll
        for (int jj=0;jj<4;jj++) {
            int n = lane + 32*jj;
            float add = tre * sm[W1L_OFF+n];
            float a1  = sigf(g_prea[(long)row*128+n] + add + sm[EB1_OFF+n]);
            float pd  = g_pred[(long)row*128+n] + add;
            abuf[n] = a1;
            dbuf[n] = a1*(1.f-a1)*pd;
        }
        __syncwarp();
        // encoder layer2: 64 out of 128
        float a2v[2], d2v[2];
        #pragma unroll
        for (int jj=0;jj<2;jj++) {
            int n = lane + 32*jj;
            float s1 = sm[EB2_OFF+n], s2 = 0.f;
            #pragma unroll 8
            for (int k=0;k<128;k++) {
                float wv = sm[W2T_OFF + k*64 + n];
                s1 = fmaf(abuf[k], wv, s1);
                s2 = fmaf(dbuf[k], wv, s2);
            }
            float a = sigf(s1);
            a2v[jj] = a; d2v[jj] = a*(1.f-a)*s2;
        }
        __syncwarp();
        abuf[lane]=a2v[0]; abuf[lane+32]=a2v[1];
        dbuf[lane]=d2v[0]; dbuf[lane+32]=d2v[1];
        __syncwarp();
        // encoder layer3: 32 out of 64
        {
            float s1 = sm[EB3_OFF+lane], s2 = 0.f;
            #pragma unroll 8
            for (int k=0;k<64;k++) {
                float wv = sm[W3T_OFF + k*32 + lane];
                s1 = fmaf(abuf[k], wv, s1);
                s2 = fmaf(dbuf[k], wv, s2);
            }
            float a = sigf(s1);
            float d = a*(1.f-a)*s2;
            __syncwarp();
            abuf[lane] = a; dbuf[lane] = d;
        }
        __syncwarp();
        // z and z_dot_true (each lane computes all 3; smem broadcasts)
        float zz[3], zt[3];
        #pragma unroll
        for (int j=0;j<3;j++) {
            float s1 = sm[EB4_OFF+j], s2 = 0.f;
            #pragma unroll
            for (int k=0;k<32;k++) {
                float wv = sm[W4S_OFF + j*32 + k];
                s1 = fmaf(abuf[k], wv, s1);
                s2 = fmaf(dbuf[k], wv, s2);
            }
            zz[j]=s1; zt[j]=s2;
        }
        const float s = zz[0], d = zz[1], t3 = zz[2];
        // theta @ coefficients
        float th[7] = {1.f, s, s*s, s*d, s*t3, s*s*d, s*s*t3};
        float zp[3] = {0.f,0.f,0.f};
        #pragma unroll
        for (int i=0;i<7;i++) {
            zp[0] = fmaf(th[i], sm[COEF_OFF+i*3+0], zp[0]);
            zp[1] = fmaf(th[i], sm[COEF_OFF+i*3+1], zp[1]);
            zp[2] = fmaf(th[i], sm[COEF_OFF+i*3+2], zp[2]);
        }
        if (lane == 0) {
            float dpo = s - size_[row];
            po += dpo*dpo;
            float l = t3;
            tr += fmaxf(l, 0.f) + log1pf(expf(-fabsf(l))) - l*tre;
            float e0 = zt[0]-zp[0], e1 = zt[1]-zp[1], e2 = zt[2]-zp[2];
            szl += e0*e0 + e1*e1 + e2*e2;
        }
        if (lane < 3) out[(long)row*3 + lane] = zz[lane];
        __syncwarp();
        // decoder layer1: 32 out of 3
        {
            float w0 = sm[DW1T_OFF + 0*32 + lane];
            float w1 = sm[DW1T_OFF + 1*32 + lane];
            float w2 = sm[DW1T_OFF + 2*32 + lane];
            float h  = sigf(sm[DB1_OFF+lane] + s*w0 + d*w1 + t3*w2);
            float pd = zp[0]*w0 + zp[1]*w1 + zp[2]*w2;
            abuf[lane] = h; dbuf[lane] = h*(1.f-h)*pd;
        }
        __syncwarp();
        // decoder layer2: 64 out of 32
        float h2v[2], dd2v[2];
        #pragma unroll
        for (int jj=0;jj<2;jj++) {
            int n = lane + 32*jj;
            float s1 = sm[DB2_OFF+n], s2 = 0.f;
            #pragma unroll
            for (int k=0;k<32;k++) {
                float wv = sm[DW2T_OFF + k*64 + n];
                s1 = fmaf(abuf[k], wv, s1);
                s2 = fmaf(dbuf[k], wv, s2);
            }
            float h = sigf(s1);
            h2v[jj]=h; dd2v[jj]=h*(1.f-h)*s2;
        }
        __syncwarp();
        abuf[lane]=h2v[0]; abuf[lane+32]=h2v[1];
        dbuf[lane]=dd2v[0]; dbuf[lane+32]=dd2v[1];
        __syncwarp();
        // decoder layer3: 128 out of 64 -> global
        #pragma unroll
        for (int jj=0;jj<4;jj++) {
            int n = lane + 32*jj;
            float s1 = sm[DB3_OFF+n], s2 = 0.f;
            #pragma unroll 8
            for (int k=0;k<64;k++) {
                float wv = sm[DW3T_OFF + k*128 + n];
                s1 = fmaf(abuf[k], wv, s1);
                s2 = fmaf(dbuf[k], wv, s2);
            }
            float h = sigf(s1);
            g_h3  [(long)row*128+n] = h;
            g_dzd3[(long)row*128+n] = h*(1.f-h)*s2;
        }
        __syncwarp();
    }
    // deterministic loss partials
    if (lane == 0) {
        sm[LRED_OFF + w]      = po;
        sm[LRED_OFF + 8 + w]  = tr;
        sm[LRED_OFF + 16 + w] = szl;
    }
    __syncthreads();
    if (tid == 0) {
        float a=0.f,b=0.f,c=0.f;
        for (int i=0;i<8;i++){ a+=sm[LRED_OFF+i]; b+=sm[LRED_OFF+8+i]; c+=sm[LRED_OFF+16+i]; }
        g_part_po[blockIdx.x]=a; g_part_tr[blockIdx.x]=b; g_part_sz[blockIdx.x]=c;
    }
}

// ================= K3: big GEMM (M=16384, N=2048, K=128) tf32x3 + fused losses ====
__global__ void __launch_bounds__(256) k3_gemm(
    const float* __restrict__ dW4, const float* __restrict__ db4,
    const float* __restrict__ x, const float* __restrict__ x_dot,
    float* __restrict__ out)
{
    __shared__ float As[128*36];
    __shared__ float Bs[128*36];
    __shared__ float red[256];
    const int path = blockIdx.z;
    const float* A = (path == 0) ? g_h3 : g_dzd3;
    const int m0 = blockIdx.y * 128;
    const int n0 = blockIdx.x * 128;
    const int tid = threadIdx.x;
    const int w  = tid >> 5;
    const int wr = w >> 2;
    const int wc = w & 3;

    wmma::fragment<wmma::accumulator,16,16,8,float> acc[4][2];
    #pragma unroll
    for (int i=0;i<4;i++)
        #pragma unroll
        for(int j=0;j<2;j++) wmma::fill_fragment(acc[i][j], 0.0f);

    for (int k0 = 0; k0 < 128; k0 += 32) {
        {
            const float4* src = reinterpret_cast<const float4*>(A);
            #pragma unroll
            for (int i = 0; i < 4; i++) {
                int p = tid + 256*i; int r = p >> 3; int c4 = p & 7;
                float4 v = src[(long)(m0 + r) * 32 + (k0 >> 2) + c4];
                *reinterpret_cast<float4*>(&As[r*36 + c4*4]) = v;
            }
        }
        {
            const float4* src = reinterpret_cast<const float4*>(dW4);
            #pragma unroll
            for (int i = 0; i < 4; i++) {
                int p = tid + 256*i; int r = p >> 3; int c4 = p & 7;
                float4 v = src[(long)(n0 + r) * 32 + (k0 >> 2) + c4];
                *reinterpret_cast<float4*>(&Bs[r*36 + c4*4]) = v;
            }
        }
        __syncthreads();
        #pragma unroll
        for (int kk = 0; kk < 32; kk += 8) {
            wmma::fragment<wmma::matrix_b,16,16,8,wmma::precision::tf32,wmma::col_major> bh[2], bl[2];
            #pragma unroll
            for (int j=0;j<2;j++) {
                wmma::fragment<wmma::matrix_b,16,16,8,wmma::precision::tf32,wmma::col_major> braw;
                wmma::load_matrix_sync(braw, &Bs[(wc*32 + j*16)*36 + kk], 36);
                #pragma unroll
                for (int e=0;e<braw.num_elements;e++) {
                    float v  = braw.x[e];
                    float hi = wmma::__float_to_tf32(v);
                    bh[j].x[e] = hi;
                    bl[j].x[e] = wmma::__float_to_tf32(v - hi);
                }
            }
            #pragma unroll
            for (int i=0;i<4;i++) {
                wmma::fragment<wmma::matrix_a,16,16,8,wmma::precision::tf32,wmma::row_major> araw, ah, al;
                wmma::load_matrix_sync(araw, &As[(wr*64 + i*16)*36 + kk], 36);
                #pragma unroll
                for (int e=0;e<araw.num_elements;e++) {
                    float v  = araw.x[e];
                    float hi = wmma::__float_to_tf32(v);
                    ah.x[e] = hi;
                    al.x[e] = wmma::__float_to_tf32(v - hi);
                }
                #pragma unroll
                for (int j=0;j<2;j++) {
                    wmma::mma_sync(acc[i][j], ah, bh[j], acc[i][j]);
                    wmma::mma_sync(acc[i][j], al, bh[j], acc[i][j]);
                    wmma::mma_sync(acc[i][j], ah, bl[j], acc[i][j]);
                }
            }
        }
        __syncthreads();
    }
    __syncthreads();
    // epilogue: per-warp staging in As, fused bias+store+loss
    float lacc = 0.f;
    float* stage = As + w * 336;   // 16x20 region per warp
    #pragma unroll
    for (int i=0;i<4;i++) {
        #pragma unroll
        for (int j=0;j<2;j++) {
            wmma::store_matrix_sync(stage, acc[i][j], 20, wmma::mem_row_major);
            __syncwarp();
            const int mbase = m0 + wr*64 + i*16;
            const int nbase = n0 + wc*32 + j*16;
            #pragma unroll
            for (int q=0;q<8;q++) {
                int e = (tid & 31) + 32*q;
                int r = e >> 4, c = e & 15;
                float v = stage[r*20 + c];
                long m = mbase + r; long n = nbase + c;
                if (path == 0) {
                    v += db4[n];
                    out[XHAT_OFF + m*2048 + n] = v;
                    float df = v - x[m*2048 + n];
                    lacc += df*df;
                } else {
                    float df = v - x_dot[m*2048 + n];
                    lacc += df*df;
                }
            }
            __syncwarp();
        }
    }
    red[tid] = lacc;
    __syncthreads();
    for (int sft = 128; sft > 0; sft >>= 1) {
        if (tid < sft) red[tid] += red[tid + sft];
        __syncthreads();
    }
    if (tid == 0) {
        int idx = blockIdx.y*16 + blockIdx.x;
        if (path == 0) g_part_rec[idx] = red[0];
        else           g_part_sx[idx]  = red[0];
    }
}

// ================= K4: deterministic finalize =================
__global__ void k4_final(const float* __restrict__ coef, float* __restrict__ out) {
    const int w = threadIdx.x >> 5, lane = threadIdx.x & 31;
    float s = 0.f;
    if      (w == 0) { for (int i=lane;i<512;i+=32)  s += g_part_po[i]; }
    else if (w == 1) { for (int i=lane;i<512;i+=32)  s += g_part_tr[i]; }
    else if (w == 2) { for (int i=lane;i<512;i+=32)  s += g_part_sz[i]; }
    else if (w == 3) { for (int i=lane;i<2048;i+=32) s += g_part_rec[i]; }
    else if (w == 4) { for (int i=lane;i<2048;i+=32) s += g_part_sx[i]; }
    else             { for (int i=lane;i<21;i+=32)   s += fabsf(coef[i]); }
    #pragma unroll
    for (int o=16;o>0;o>>=1) s += __shfl_down_sync(0xffffffffu, s, o);
    if (lane == 0) {
        if      (w == 0) out[SCAL_OFF+0] = s / 16384.f;                 // loss_po
        else if (w == 1) out[SCAL_OFF+1] = s / 16384.f;                 // loss_tr
        else if (w == 2) out[SCAL_OFF+4] = s / (16384.f*3.f);           // sindy_z
        else if (w == 3) out[SCAL_OFF+2] = s / (16384.f*2048.f);        // recon
        else if (w == 4) out[SCAL_OFF+3] = s / (16384.f*2048.f);        // sindy_x
        else             out[SCAL_OFF+5] = s / 21.f;                    // l1
    }
}

// ================= launch =================
extern "C" void kernel_launch(void* const* d_in, const int* in_sizes, int n_in,
                              void* d_out, int out_size) {
    const float* x         = (const float*)d_in[0];
    const float* x_dot     = (const float*)d_in[1];
    const float* treatment = (const float*)d_in[2];
    const float* size_     = (const float*)d_in[3];
    const float* eW1 = (const float*)d_in[4];  const float* eb1 = (const float*)d_in[5];
    const float* eW2 = (const float*)d_in[6];  const float* eb2 = (const float*)d_in[7];
    const float* eW3 = (const float*)d_in[8];  const float* eb3 = (const float*)d_in[9];
    const float* eW4 = (const float*)d_in[10]; const float* eb4 = (const float*)d_in[11];
    const float* dW1 = (const float*)d_in[12]; const float* db1 = (const float*)d_in[13];
    const float* dW2 = (const float*)d_in[14]; const float* db2 = (const float*)d_in[15];
    const float* dW3 = (const float*)d_in[16]; const float* db3 = (const float*)d_in[17];
    const float* dW4 = (const float*)d_in[18]; const float* db4 = (const float*)d_in[19];
    const float* coef = (const float*)d_in[20];
    float* out = (float*)d_out;

    cudaFuncSetAttribute(k2_chain, cudaFuncAttributeMaxDynamicSharedMemorySize, K2_SMEM);

    k1_gemm<<<dim3(128, 2), 256>>>(x, x_dot, eW1);
    k2_chain<<<512, 256, K2_SMEM>>>(treatment, size_, eW1, eb1, eW2, eb2, eW3, eb3,
                                    eW4, eb4, dW1, db1, dW2, db2, dW3, db3, coef, out);
    k3_gemm<<<dim3(16, 128, 2), 256>>>(dW4, db4, x, x_dot, out);
    k4_final<<<1, 192>>>(coef, out);
}

// round 2
// speedup vs baseline: 1.9448x; 1.9448x over previous
#include <cuda_runtime.h>
#include <cuda_bf16.h>
#include <mma.h>

using namespace nvcuda;

#define B_SZ   16384
#define DIN    2048
#define XHAT_OFF (16384L*3)
#define SCAL_OFF (16384L*3 + 16384L*2048)
#define TS 80            // padded bf16 smem row stride (160B: 32B-aligned rows)
#define GEMM_SMEM (4*128*TS*2)

// ---------------- scratch (device globals; no allocation allowed) ----------------
__device__ float g_prea[B_SZ*128];   // x-path pre-activation (no bias, no treatment col)
__device__ float g_pred[B_SZ*128];   // x_dot-path
__device__ __nv_bfloat16 g_h3h[B_SZ*128];
__device__ __nv_bfloat16 g_h3l[B_SZ*128];
__device__ __nv_bfloat16 g_d3h[B_SZ*128];
__device__ __nv_bfloat16 g_eW1h[128*2048];
__device__ __nv_bfloat16 g_eW1l[128*2048];
__device__ __nv_bfloat16 g_dW4h[2048*128];
__device__ __nv_bfloat16 g_dW4l[2048*128];
__device__ float g_part_po[512], g_part_tr[512], g_part_sz[512];
__device__ float g_part_rec[2048], g_part_sx[2048];

__device__ __forceinline__ void split2(float v, __nv_bfloat16& h, __nv_bfloat16& l) {
    h = __float2bfloat16(v);
    l = __float2bfloat16(v - __bfloat162float(h));
}
__device__ __forceinline__ unsigned pk(__nv_bfloat16 a, __nv_bfloat16 b) {
    __nv_bfloat162 t = __halves2bfloat162(a, b);
    return *reinterpret_cast<unsigned*>(&t);
}

// ================= K0: pre-split weights into bf16 hi/lo =================
__global__ void __launch_bounds__(256) k0_prep(const float* __restrict__ eW1,
                                               const float* __restrict__ dW4) {
    int i = blockIdx.x * 256 + threadIdx.x;
    if (i < 128*2048) {
        int n = i >> 11, k = i & 2047;
        split2(eW1[n*2049 + k], g_eW1h[i], g_eW1l[i]);
    }
    if (i < 2048*128) {
        split2(dW4[i], g_dW4h[i], g_dW4l[i]);
    }
}

// ================= K1: GEMM (M=16384, N=128, K=2048) bf16x3 =================
__global__ void __launch_bounds__(256) k1_gemm(
    const float* __restrict__ x, const float* __restrict__ x_dot)
{
    extern __shared__ __nv_bfloat16 smb[];
    __nv_bfloat16* Ah = smb;
    __nv_bfloat16* Al = smb + 128*TS;
    __nv_bfloat16* Bh = smb + 2*128*TS;
    __nv_bfloat16* Bl = smb + 3*128*TS;

    const int path = blockIdx.y;
    const float* A = (path == 0) ? x : x_dot;
    float* Out = (path == 0) ? g_prea : g_pred;
    const int m0 = blockIdx.x * 128;
    const int tid = threadIdx.x;
    const int w  = tid >> 5;
    const int wr = w >> 2;     // 0..1
    const int wc = w & 3;      // 0..3

    wmma::fragment<wmma::accumulator,16,16,16,float> acc[4][2];
    #pragma unroll
    for (int i=0;i<4;i++)
        #pragma unroll
        for(int j=0;j<2;j++) wmma::fill_fragment(acc[i][j], 0.0f);

    for (int k0 = 0; k0 < 2048; k0 += 64) {
        // A tile 128x64: fp32 -> split bf16 hi/lo
        {
            const float4* src = reinterpret_cast<const float4*>(A);
            #pragma unroll
            for (int i = 0; i < 8; i++) {
                int p  = tid + 256*i;          // 0..2047
                int r  = p >> 4;
                int c4 = p & 15;
                float4 v = src[(long)(m0 + r) * 512 + (k0 >> 2) + c4];
                __nv_bfloat16 h0,h1,h2,h3,l0,l1,l2,l3;
                split2(v.x,h0,l0); split2(v.y,h1,l1);
                split2(v.z,h2,l2); split2(v.w,h3,l3);
                unsigned* ph = reinterpret_cast<unsigned*>(&Ah[r*TS + c4*4]);
                unsigned* pl = reinterpret_cast<unsigned*>(&Al[r*TS + c4*4]);
                ph[0] = pk(h0,h1); ph[1] = pk(h2,h3);
                pl[0] = pk(l0,l1); pl[1] = pk(l2,l3);
            }
        }
        // B tile 128x64 from pre-split eW1 (u32 copies)
        {
            #pragma unroll
            for (int i = 0; i < 16; i++) {
                int p  = tid + 256*i;          // 0..4095 u32
                int n  = p >> 5;
                int c2 = p & 31;
                unsigned vh = reinterpret_cast<const unsigned*>(g_eW1h)[n*1024 + (k0>>1) + c2];
                unsigned vl = reinterpret_cast<const unsigned*>(g_eW1l)[n*1024 + (k0>>1) + c2];
                *reinterpret_cast<unsigned*>(&Bh[n*TS + c2*2]) = vh;
                *reinterpret_cast<unsigned*>(&Bl[n*TS + c2*2]) = vl;
            }
        }
        __syncthreads();
        #pragma unroll
        for (int kk = 0; kk < 64; kk += 16) {
            wmma::fragment<wmma::matrix_b,16,16,16,__nv_bfloat16,wmma::col_major> bh[2], bl[2];
            #pragma unroll
            for (int j=0;j<2;j++) {
                wmma::load_matrix_sync(bh[j], &Bh[(wc*32 + j*16)*TS + kk], TS);
                wmma::load_matrix_sync(bl[j], &Bl[(wc*32 + j*16)*TS + kk], TS);
            }
            #pragma unroll
            for (int i=0;i<4;i++) {
                wmma::fragment<wmma::matrix_a,16,16,16,__nv_bfloat16,wmma::row_major> ah, al;
                wmma::load_matrix_sync(ah, &Ah[(wr*64 + i*16)*TS + kk], TS);
                wmma::load_matrix_sync(al, &Al[(wr*64 + i*16)*TS + kk], TS);
                #pragma unroll
                for (int j=0;j<2;j++) {
                    wmma::mma_sync(acc[i][j], ah, bh[j], acc[i][j]);
                    wmma::mma_sync(acc[i][j], al, bh[j], acc[i][j]);
                    wmma::mma_sync(acc[i][j], ah, bl[j], acc[i][j]);
                }
            }
        }
        __syncthreads();
    }
    #pragma unroll
    for (int i=0;i<4;i++)
        #pragma unroll
        for (int j=0;j<2;j++) {
            float* p = Out + (long)(m0 + wr*64 + i*16)*128 + wc*32 + j*16;
            wmma::store_matrix_sync(p, acc[i][j], 128, wmma::mem_row_major);
        }
}

// ================= K2: fused middle chain (warp-per-row) =================
#define W2T_OFF   0
#define W3T_OFF   (W2T_OFF + 128*64)
#define W4S_OFF   (W3T_OFF + 64*32)
#define DW1T_OFF  (W4S_OFF + 96)
#define DW2T_OFF  (DW1T_OFF + 96)
#define DW3T_OFF  (DW2T_OFF + 32*64)
#define EB1_OFF   (DW3T_OFF + 64*128)
#define EB2_OFF   (EB1_OFF + 128)
#define EB3_OFF   (EB2_OFF + 64)
#define EB4_OFF   (EB3_OFF + 32)
#define DB1_OFF   (EB4_OFF + 4)
#define DB2_OFF   (DB1_OFF + 32)
#define DB3_OFF   (DB2_OFF + 64)
#define W1L_OFF   (DB3_OFF + 128)
#define COEF_OFF  (W1L_OFF + 128)
#define BUF_OFF   (COEF_OFF + 24)
#define LRED_OFF  (BUF_OFF + 8*256)
#define K2_FLOATS (LRED_OFF + 24)
#define K2_SMEM   (K2_FLOATS * 4)

__device__ __forceinline__ float sigf(float x) { return 1.f/(1.f+__expf(-x)); }

__global__ void __launch_bounds__(256) k2_chain(
    const float* __restrict__ treatment, const float* __restrict__ size_,
    const float* __restrict__ eW1, const float* __restrict__ eb1,
    const float* __restrict__ eW2, const float* __restrict__ eb2,
    const float* __restrict__ eW3, const float* __restrict__ eb3,
    const float* __restrict__ eW4, const float* __restrict__ eb4,
    const float* __restrict__ dW1, const float* __restrict__ db1,
    const float* __restrict__ dW2, const float* __restrict__ db2,
    const float* __restrict__ dW3, const float* __restrict__ db3,
    const float* __restrict__ coef,
    float* __restrict__ out)
{
    extern __shared__ float sm[];
    const int tid = threadIdx.x;

    for (int i = tid; i < 64*128; i += 256) { int n=i>>7, k=i&127; sm[W2T_OFF + k*64 + n] = eW2[i]; }
    for (int i = tid; i < 32*64;  i += 256) { int n=i>>6, k=i&63;  sm[W3T_OFF + k*32 + n] = eW3[i]; }
    for (int i = tid; i < 3*32;   i += 256) sm[W4S_OFF + i] = eW4[i];
    for (int i = tid; i < 32*3;   i += 256) { int n=i/3,  k=i%3;  sm[DW1T_OFF + k*32 + n] = dW1[i]; }
    for (int i = tid; i < 64*32;  i += 256) { int n=i>>5, k=i&31; sm[DW2T_OFF + k*64 + n] = dW2[i]; }
    for (int i = tid; i < 128*64; i += 256) { int n=i>>6, k=i&63; sm[DW3T_OFF + k*128 + n] = dW3[i]; }
    if (tid < 128) sm[EB1_OFF+tid] = eb1[tid];
    if (tid < 64)  sm[EB2_OFF+tid] = eb2[tid];
    if (tid < 32)  sm[EB3_OFF+tid] = eb3[tid];
    if (tid < 3)   sm[EB4_OFF+tid] = eb4[tid];
    if (tid < 32)  sm[DB1_OFF+tid] = db1[tid];
    if (tid < 64)  sm[DB2_OFF+tid] = db2[tid];
    if (tid < 128) sm[DB3_OFF+tid] = db3[tid];
    if (tid < 128) sm[W1L_OFF+tid] = eW1[tid*2049 + 2048];
    if (tid < 21)  sm[COEF_OFF+tid] = coef[tid];
    __syncthreads();

    const int w = tid >> 5, lane = tid & 31;
    float* abuf = sm + BUF_OFF + w*256;
    float* dbuf = abuf + 128;
    float po = 0.f, tr = 0.f, szl = 0.f;

    for (int rr = 0; rr < 4; rr++) {
        const int row = (blockIdx.x*8 + w)*4 + rr;
        const float tre = treatment[row];

        #pragma unroll
        for (int jj=0;jj<4;jj++) {
            int n = lane + 32*jj;
            float add = tre * sm[W1L_OFF+n];
            float a1  = sigf(g_prea[(long)row*128+n] + add + sm[EB1_OFF+n]);
            float pd  = g_pred[(long)row*128+n] + add;
            abuf[n] = a1;
            dbuf[n] = a1*(1.f-a1)*pd;
        }
        __syncwarp();
        float a2v[2], d2v[2];
        #pragma unroll
        for (int jj=0;jj<2;jj++) {
            int n = lane + 32*jj;
            float s1 = sm[EB2_OFF+n], s2 = 0.f;
            #pragma unroll 8
            for (int k=0;k<128;k++) {
                float wv = sm[W2T_OFF + k*64 + n];
                s1 = fmaf(abuf[k], wv, s1);
                s2 = fmaf(dbuf[k], wv, s2);
            }
            float a = sigf(s1);
            a2v[jj] = a; d2v[jj] = a*(1.f-a)*s2;
        }
        __syncwarp();
        abuf[lane]=a2v[0]; abuf[lane+32]=a2v[1];
        dbuf[lane]=d2v[0]; dbuf[lane+32]=d2v[1];
        __syncwarp();
        {
            float s1 = sm[EB3_OFF+lane], s2 = 0.f;
            #pragma unroll 8
            for (int k=0;k<64;k++) {
                float wv = sm[W3T_OFF + k*32 + lane];
                s1 = fmaf(abuf[k], wv, s1);
                s2 = fmaf(dbuf[k], wv, s2);
            }
            float a = sigf(s1);
            float d = a*(1.f-a)*s2;
            __syncwarp();
            abuf[lane] = a; dbuf[lane] = d;
        }
        __syncwarp();
        float zz[3], zt[3];
        #pragma unroll
        for (int j=0;j<3;j++) {
            float s1 = sm[EB4_OFF+j], s2 = 0.f;
            #pragma unroll
            for (int k=0;k<32;k++) {
                float wv = sm[W4S_OFF + j*32 + k];
                s1 = fmaf(abuf[k], wv, s1);
                s2 = fmaf(dbuf[k], wv, s2);
            }
            zz[j]=s1; zt[j]=s2;
        }
        const float s = zz[0], d = zz[1], t3 = zz[2];
        float th[7] = {1.f, s, s*s, s*d, s*t3, s*s*d, s*s*t3};
        float zp[3] = {0.f,0.f,0.f};
        #pragma unroll
        for (int i=0;i<7;i++) {
            zp[0] = fmaf(th[i], sm[COEF_OFF+i*3+0], zp[0]);
            zp[1] = fmaf(th[i], sm[COEF_OFF+i*3+1], zp[1]);
            zp[2] = fmaf(th[i], sm[COEF_OFF+i*3+2], zp[2]);
        }
        if (lane == 0) {
            float dpo = s - size_[row];
            po += dpo*dpo;
            float l = t3;
            tr += fmaxf(l, 0.f) + log1pf(expf(-fabsf(l))) - l*tre;
            float e0 = zt[0]-zp[0], e1 = zt[1]-zp[1], e2 = zt[2]-zp[2];
            szl += e0*e0 + e1*e1 + e2*e2;
        }
        if (lane < 3) out[(long)row*3 + lane] = zz[lane];
        __syncwarp();
        {
            float w0 = sm[DW1T_OFF + 0*32 + lane];
            float w1 = sm[DW1T_OFF + 1*32 + lane];
            float w2 = sm[DW1T_OFF + 2*32 + lane];
            float h  = sigf(sm[DB1_OFF+lane] + s*w0 + d*w1 + t3*w2);
            float pd = zp[0]*w0 + zp[1]*w1 + zp[2]*w2;
            abuf[lane] = h; dbuf[lane] = h*(1.f-h)*pd;
        }
        __syncwarp();
        float h2v[2], dd2v[2];
        #pragma unroll
        for (int jj=0;jj<2;jj++) {
            int n = lane + 32*jj;
            float s1 = sm[DB2_OFF+n], s2 = 0.f;
            #pragma unroll
            for (int k=0;k<32;k++) {
                float wv = sm[DW2T_OFF + k*64 + n];
                s1 = fmaf(abuf[k], wv, s1);
                s2 = fmaf(dbuf[k], wv, s2);
            }
            float h = sigf(s1);
            h2v[jj]=h; dd2v[jj]=h*(1.f-h)*s2;
        }
        __syncwarp();
        abuf[lane]=h2v[0]; abuf[lane+32]=h2v[1];
        dbuf[lane]=dd2v[0]; dbuf[lane+32]=dd2v[1];
        __syncwarp();
        #pragma unroll
        for (int jj=0;jj<4;jj++) {
            int n = lane + 32*jj;
            float s1 = sm[DB3_OFF+n], s2 = 0.f;
            #pragma unroll 8
            for (int k=0;k<64;k++) {
                float wv = sm[DW3T_OFF + k*128 + n];
                s1 = fmaf(abuf[k], wv, s1);
                s2 = fmaf(dbuf[k], wv, s2);
            }
            float h = sigf(s1);
            float hd = h*(1.f-h)*s2;
            long idx = (long)row*128 + n;
            __nv_bfloat16 hh, hl;
            split2(h, hh, hl);
            g_h3h[idx] = hh;
            g_h3l[idx] = hl;
            g_d3h[idx] = __float2bfloat16(hd);
        }
        __syncwarp();
    }
    if (lane == 0) {
        sm[LRED_OFF + w]      = po;
        sm[LRED_OFF + 8 + w]  = tr;
        sm[LRED_OFF + 16 + w] = szl;
    }
    __syncthreads();
    if (tid == 0) {
        float a=0.f,b=0.f,c=0.f;
        for (int i=0;i<8;i++){ a+=sm[LRED_OFF+i]; b+=sm[LRED_OFF+8+i]; c+=sm[LRED_OFF+16+i]; }
        g_part_po[blockIdx.x]=a; g_part_tr[blockIdx.x]=b; g_part_sz[blockIdx.x]=c;
    }
}

// ================= K3: GEMM (M=16384, N=2048, K=128) bf16 + fused losses ====
// path 0: x_hat = h3 @ dW4.T + db4 (3-pass, elementwise output)
// path 1: x_dot_pred = dzd3 @ dW4.T (1-pass, scalar loss only)
__global__ void __launch_bounds__(256) k3_gemm(
    const float* __restrict__ db4,
    const float* __restrict__ x, const float* __restrict__ x_dot,
    float* __restrict__ out)
{
    extern __shared__ __nv_bfloat16 smb[];
    __shared__ float red[256];
    __nv_bfloat16* Ah = smb;
    __nv_bfloat16* Al = smb + 128*TS;
    __nv_bfloat16* Bh = smb + 2*128*TS;
    __nv_bfloat16* Bl = smb + 3*128*TS;
    float* smf = reinterpret_cast<float*>(smb);

    const int path = blockIdx.z;
    const __nv_bfloat16* Ahg = (path == 0) ? g_h3h : g_d3h;
    const int m0 = blockIdx.y * 128;
    const int n0 = blockIdx.x * 128;
    const int tid = threadIdx.x;
    const int w  = tid >> 5;
    const int wr = w >> 2;
    const int wc = w & 3;

    wmma::fragment<wmma::accumulator,16,16,16,float> acc[4][2];
    #pragma unroll
    for (int i=0;i<4;i++)
        #pragma unroll
        for(int j=0;j<2;j++) wmma::fill_fragment(acc[i][j], 0.0f);

    for (int k0 = 0; k0 < 128; k0 += 64) {
        #pragma unroll
        for (int i = 0; i < 16; i++) {
            int p  = tid + 256*i;     // 0..4095 u32
            int r  = p >> 5;
            int c2 = p & 31;
            unsigned v = reinterpret_cast<const unsigned*>(Ahg)[(long)(m0+r)*64 + (k0>>1) + c2];
            *reinterpret_cast<unsigned*>(&Ah[r*TS + c2*2]) = v;
            unsigned bv = reinterpret_cast<const unsigned*>(g_dW4h)[(n0+r)*64 + (k0>>1) + c2];
            *reinterpret_cast<unsigned*>(&Bh[r*TS + c2*2]) = bv;
            if (path == 0) {
                unsigned v2 = reinterpret_cast<const unsigned*>(g_h3l)[(long)(m0+r)*64 + (k0>>1) + c2];
                *reinterpret_cast<unsigned*>(&Al[r*TS + c2*2]) = v2;
                unsigned b2 = reinterpret_cast<const unsigned*>(g_dW4l)[(n0+r)*64 + (k0>>1) + c2];
                *reinterpret_cast<unsigned*>(&Bl[r*TS + c2*2]) = b2;
            }
        }
        __syncthreads();
        #pragma unroll
        for (int kk = 0; kk < 64; kk += 16) {
            wmma::fragment<wmma::matrix_b,16,16,16,__nv_bfloat16,wmma::col_major> bh[2], bl[2];
            #pragma unroll
            for (int j=0;j<2;j++) {
                wmma::load_matrix_sync(bh[j], &Bh[(wc*32 + j*16)*TS + kk], TS);
                if (path == 0)
                    wmma::load_matrix_sync(bl[j], &Bl[(wc*32 + j*16)*TS + kk], TS);
            }
            #pragma unroll
            for (int i=0;i<4;i++) {
                wmma::fragment<wmma::matrix_a,16,16,16,__nv_bfloat16,wmma::row_major> ah, al;
                wmma::load_matrix_sync(ah, &Ah[(wr*64 + i*16)*TS + kk], TS);
                if (path == 0)
                    wmma::load_matrix_sync(al, &Al[(wr*64 + i*16)*TS + kk], TS);
                #pragma unroll
                for (int j=0;j<2;j++) {
                    wmma::mma_sync(acc[i][j], ah, bh[j], acc[i][j]);
                    if (path == 0) {
                        wmma::mma_sync(acc[i][j], al, bh[j], acc[i][j]);
                        wmma::mma_sync(acc[i][j], ah, bl[j], acc[i][j]);
                    }
                }
            }
        }
        __syncthreads();
    }
    // epilogue: per-warp staging, fused bias+store+loss
    float lacc = 0.f;
    float* stage = smf + w * 336;
    #pragma unroll
    for (int i=0;i<4;i++) {
        #pragma unroll
        for (int j=0;j<2;j++) {
            wmma::store_matrix_sync(stage, acc[i][j], 20, wmma::mem_row_major);
            __syncwarp();
            const int mbase = m0 + wr*64 + i*16;
            const int nbase = n0 + wc*32 + j*16;
            #pragma unroll
            for (int q=0;q<8;q++) {
                int e = (tid & 31) + 32*q;
                int r = e >> 4, c = e & 15;
                float v = stage[r*20 + c];
                long m = mbase + r; long n = nbase + c;
                if (path == 0) {
                    v += db4[n];
                    out[XHAT_OFF + m*2048 + n] = v;
                    float df = v - x[m*2048 + n];
                    lacc += df*df;
                } else {
                    float df = v - x_dot[m*2048 + n];
                    lacc += df*df;
                }
            }
            __syncwarp();
        }
    }
    red[tid] = lacc;
    __syncthreads();
    for (int sft = 128; sft > 0; sft >>= 1) {
        if (tid < sft) red[tid] += red[tid + sft];
        __syncthreads();
    }
    if (tid == 0) {
        int idx = blockIdx.y*16 + blockIdx.x;
        if (path == 0) g_part_rec[idx] = red[0];
        else           g_part_sx[idx]  = red[0];
    }
}

// ================= K4: deterministic finalize =================
__global__ void k4_final(const float* __restrict__ coef, float* __restrict__ out) {
    const int w = threadIdx.x >> 5, lane = threadIdx.x & 31;
    float s = 0.f;
    if      (w == 0) { for (int i=lane;i<512;i+=32)  s += g_part_po[i]; }
    else if (w == 1) { for (int i=lane;i<512;i+=32)  s += g_part_tr[i]; }
    else if (w == 2) { for (int i=lane;i<512;i+=32)  s += g_part_sz[i]; }
    else if (w == 3) { for (int i=lane;i<2048;i+=32) s += g_part_rec[i]; }
    else if (w == 4) { for (int i=lane;i<2048;i+=32) s += g_part_sx[i]; }
    else             { for (int i=lane;i<21;i+=32)   s += fabsf(coef[i]); }
    #pragma unroll
    for (int o=16;o>0;o>>=1) s += __shfl_down_sync(0xffffffffu, s, o);
    if (lane == 0) {
        if      (w == 0) out[SCAL_OFF+0] = s / 16384.f;
        else if (w == 1) out[SCAL_OFF+1] = s / 16384.f;
        else if (w == 2) out[SCAL_OFF+4] = s / (16384.f*3.f);
        else if (w == 3) out[SCAL_OFF+2] = s / (16384.f*2048.f);
        else if (w == 4) out[SCAL_OFF+3] = s / (16384.f*2048.f);
        else             out[SCAL_OFF+5] = s / 21.f;
    }
}

// ================= launch =================
extern "C" void kernel_launch(void* const* d_in, const int* in_sizes, int n_in,
                              void* d_out, int out_size) {
    const float* x         = (const float*)d_in[0];
    const float* x_dot     = (const float*)d_in[1];
    const float* treatment = (const float*)d_in[2];
    const float* size_     = (const float*)d_in[3];
    const float* eW1 = (const float*)d_in[4];  const float* eb1 = (const float*)d_in[5];
    const float* eW2 = (const float*)d_in[6];  const float* eb2 = (const float*)d_in[7];
    const float* eW3 = (const float*)d_in[8];  const float* eb3 = (const float*)d_in[9];
    const float* eW4 = (const float*)d_in[10]; const float* eb4 = (const float*)d_in[11];
    const float* dW1 = (const float*)d_in[12]; const float* db1 = (const float*)d_in[13];
    const float* dW2 = (const float*)d_in[14]; const float* db2 = (const float*)d_in[15];
    const float* dW3 = (const float*)d_in[16]; const float* db3 = (const float*)d_in[17];
    const float* dW4 = (const float*)d_in[18]; const float* db4 = (const float*)d_in[19];
    const float* coef = (const float*)d_in[20];
    float* out = (float*)d_out;

    cudaFuncSetAttribute(k1_gemm, cudaFuncAttributeMaxDynamicSharedMemorySize, GEMM_SMEM);
    cudaFuncSetAttribute(k3_gemm, cudaFuncAttributeMaxDynamicSharedMemorySize, GEMM_SMEM);
    cudaFuncSetAttribute(k2_chain, cudaFuncAttributeMaxDynamicSharedMemorySize, K2_SMEM);

    k0_prep<<<1024, 256>>>(eW1, dW4);
    k1_gemm<<<dim3(128, 2), 256, GEMM_SMEM>>>(x, x_dot);
    k2_chain<<<512, 256, K2_SMEM>>>(treatment, size_, eW1, eb1, eW2, eb2, eW3, eb3,
                                    eW4, eb4, dW1, db1, dW2, db2, dW3, db3, coef, out);
    k3_gemm<<<dim3(16, 128, 2), 256, GEMM_SMEM>>>(db4, x, x_dot, out);
    k4_final<<<1, 192>>>(coef, out);
}

// round 3
// speedup vs baseline: 2.5086x; 1.2899x over previous
#include <cuda_runtime.h>
#include <cuda_bf16.h>
#include <mma.h>

using namespace nvcuda;

#define B_SZ   16384
#define DIN    2048
#define XHAT_OFF (16384L*3)
#define SCAL_OFF (16384L*3 + 16384L*2048)
#define TS2 40                       // bf16 smem row stride (80B; conflict-free ldmatrix)
#define STAGE_BF16 (128*TS2)         // one 128x32 tile (padded)
#define GEMM_SMEM (2*4*STAGE_BF16*2) // 2 stages * 4 arrays * bytes = 81920

// ---------------- scratch (device globals; no allocation allowed) ----------------
__device__ float g_prea[B_SZ*128];
__device__ float g_pred[B_SZ*128];
__device__ __nv_bfloat16 g_h3h[B_SZ*128];
__device__ __nv_bfloat16 g_h3l[B_SZ*128];
__device__ __nv_bfloat16 g_d3h[B_SZ*128];
__device__ __nv_bfloat16 g_eW1h[128*2048];
__device__ __nv_bfloat16 g_eW1l[128*2048];
__device__ __nv_bfloat16 g_dW4h[2048*128];
__device__ __nv_bfloat16 g_dW4l[2048*128];
__device__ float g_part_po[512], g_part_tr[512], g_part_sz[512];
__device__ float g_part_rec[2048], g_part_sx[2048];

__device__ __forceinline__ void split2(float v, __nv_bfloat16& h, __nv_bfloat16& l) {
    h = __float2bfloat16(v);
    l = __float2bfloat16(v - __bfloat162float(h));
}
__device__ __forceinline__ unsigned pk(__nv_bfloat16 a, __nv_bfloat16 b) {
    __nv_bfloat162 t = __halves2bfloat162(a, b);
    return *reinterpret_cast<unsigned*>(&t);
}
__device__ __forceinline__ void cpa16(void* sdst, const void* gsrc) {
    unsigned s = (unsigned)__cvta_generic_to_shared(sdst);
    asm volatile("cp.async.cg.shared.global [%0], [%1], 16;\n" :: "r"(s), "l"(gsrc));
}
__device__ __forceinline__ void cp_commit() { asm volatile("cp.async.commit_group;\n"); }
__device__ __forceinline__ void cp_wait1() { asm volatile("cp.async.wait_group 1;\n"); }
__device__ __forceinline__ void cp_wait0() { asm volatile("cp.async.wait_group 0;\n"); }

// ================= K0: pre-split weights into bf16 hi/lo =================
__global__ void __launch_bounds__(256) k0_prep(const float* __restrict__ eW1,
                                               const float* __restrict__ dW4) {
    int i = blockIdx.x * 256 + threadIdx.x;
    if (i < 128*2048) {
        int n = i >> 11, k = i & 2047;
        split2(eW1[n*2049 + k], g_eW1h[i], g_eW1l[i]);
    }
    if (i < 2048*128) {
        split2(dW4[i], g_dW4h[i], g_dW4l[i]);
    }
}

// ================= K1: GEMM (M=16384, N=128, K=2048) bf16x3, pipelined =================
__global__ void __launch_bounds__(256, 2) k1_gemm(
    const float* __restrict__ x, const float* __restrict__ x_dot)
{
    extern __shared__ __nv_bfloat16 smb[];
    const int path = blockIdx.y;
    const float* A = (path == 0) ? x : x_dot;
    float* Out = (path == 0) ? g_prea : g_pred;
    const int m0 = blockIdx.x * 128;
    const int tid = threadIdx.x;
    const int w  = tid >> 5;
    const int wr = w >> 2;
    const int wc = w & 3;

    const float4* Asrc = reinterpret_cast<const float4*>(A);
    const uint4*  Bhg  = reinterpret_cast<const uint4*>(g_eW1h);
    const uint4*  Blg  = reinterpret_cast<const uint4*>(g_eW1l);

    // per-thread tile coords
    const int ar  = (tid) >> 3;              // base row for A loads (with +32*i)
    const int ac4 = tid & 7;
    const int br  = tid >> 2;                // rows 0..63 (+64 for i=1)
    const int bgc = tid & 3;

    wmma::fragment<wmma::accumulator,16,16,16,float> acc[4][2];
    #pragma unroll
    for (int i=0;i<4;i++)
        #pragma unroll
        for(int j=0;j<2;j++) wmma::fill_fragment(acc[i][j], 0.0f);

    float4 areg[4];
    // ---- prologue: chunk 0 ----
    #pragma unroll
    for (int i=0;i<4;i++)
        areg[i] = Asrc[(long)(m0 + ar + 32*i)*512 + ac4];
    {
        __nv_bfloat16* Bh = smb + 2*STAGE_BF16;
        __nv_bfloat16* Bl = smb + 3*STAGE_BF16;
        #pragma unroll
        for (int i=0;i<2;i++) {
            int r = br + 64*i;
            cpa16(&Bh[r*TS2 + bgc*8], &Bhg[r*256 + bgc]);
            cpa16(&Bl[r*TS2 + bgc*8], &Blg[r*256 + bgc]);
        }
        cp_commit();
        // split+STS A chunk0 into stage0
        __nv_bfloat16* Ah = smb;
        __nv_bfloat16* Al = smb + STAGE_BF16;
        #pragma unroll
        for (int i=0;i<4;i++) {
            int r = ar + 32*i;
            float4 v = areg[i];
            __nv_bfloat16 h0,h1,h2,h3,l0,l1,l2,l3;
            split2(v.x,h0,l0); split2(v.y,h1,l1); split2(v.z,h2,l2); split2(v.w,h3,l3);
            unsigned* ph = reinterpret_cast<unsigned*>(&Ah[r*TS2 + ac4*4]);
            unsigned* pl = reinterpret_cast<unsigned*>(&Al[r*TS2 + ac4*4]);
            ph[0]=pk(h0,h1); ph[1]=pk(h2,h3);
            pl[0]=pk(l0,l1); pl[1]=pk(l2,l3);
        }
    }

    #pragma unroll 1
    for (int c = 0; c < 64; c++) {
        const int s  = c & 1;
        const int sn = s ^ 1;
        if (c < 63) {
            // prefetch chunk c+1
            #pragma unroll
            for (int i=0;i<4;i++)
                areg[i] = Asrc[(long)(m0 + ar + 32*i)*512 + (c+1)*8 + ac4];
            __nv_bfloat16* Bh = smb + sn*4*STAGE_BF16 + 2*STAGE_BF16;
            __nv_bfloat16* Bl = smb + sn*4*STAGE_BF16 + 3*STAGE_BF16;
            #pragma unroll
            for (int i=0;i<2;i++) {
                int r = br + 64*i;
                cpa16(&Bh[r*TS2 + bgc*8], &Bhg[r*256 + (c+1)*4 + bgc]);
                cpa16(&Bl[r*TS2 + bgc*8], &Blg[r*256 + (c+1)*4 + bgc]);
            }
            cp_commit();
            cp_wait1();
        } else {
            cp_wait0();
        }
        __syncthreads();
        // ---- MMA on stage s ----
        {
            __nv_bfloat16* Ah = smb + s*4*STAGE_BF16;
            __nv_bfloat16* Al = Ah + STAGE_BF16;
            __nv_bfloat16* Bh = Ah + 2*STAGE_BF16;
            __nv_bfloat16* Bl = Ah + 3*STAGE_BF16;
            #pragma unroll
            for (int kk = 0; kk < 32; kk += 16) {
                wmma::fragment<wmma::matrix_b,16,16,16,__nv_bfloat16,wmma::col_major> bh[2], bl[2];
                #pragma unroll
                for (int j=0;j<2;j++) {
                    wmma::load_matrix_sync(bh[j], &Bh[(wc*32 + j*16)*TS2 + kk], TS2);
                    wmma::load_matrix_sync(bl[j], &Bl[(wc*32 + j*16)*TS2 + kk], TS2);
                }
                #pragma unroll
                for (int i=0;i<4;i++) {
                    wmma::fragment<wmma::matrix_a,16,16,16,__nv_bfloat16,wmma::row_major> ah, al;
                    wmma::load_matrix_sync(ah, &Ah[(wr*64 + i*16)*TS2 + kk], TS2);
                    wmma::load_matrix_sync(al, &Al[(wr*64 + i*16)*TS2 + kk], TS2);
                    #pragma unroll
                    for (int j=0;j<2;j++) {
                        wmma::mma_sync(acc[i][j], ah, bh[j], acc[i][j]);
                        wmma::mma_sync(acc[i][j], al, bh[j], acc[i][j]);
                        wmma::mma_sync(acc[i][j], ah, bl[j], acc[i][j]);
                    }
                }
            }
        }
        if (c < 63) {
            __syncthreads();
            // split+STS A chunk c+1 into stage sn
            __nv_bfloat16* Ah = smb + sn*4*STAGE_BF16;
            __nv_bfloat16* Al = Ah + STAGE_BF16;
            #pragma unroll
            for (int i=0;i<4;i++) {
                int r = ar + 32*i;
                float4 v = areg[i];
                __nv_bfloat16 h0,h1,h2,h3,l0,l1,l2,l3;
                split2(v.x,h0,l0); split2(v.y,h1,l1); split2(v.z,h2,l2); split2(v.w,h3,l3);
                unsigned* ph = reinterpret_cast<unsigned*>(&Ah[r*TS2 + ac4*4]);
                unsigned* pl = reinterpret_cast<unsigned*>(&Al[r*TS2 + ac4*4]);
                ph[0]=pk(h0,h1); ph[1]=pk(h2,h3);
                pl[0]=pk(l0,l1); pl[1]=pk(l2,l3);
            }
        }
    }
    #pragma unroll
    for (int i=0;i<4;i++)
        #pragma unroll
        for (int j=0;j<2;j++) {
            float* p = Out + (long)(m0 + wr*64 + i*16)*128 + wc*32 + j*16;
            wmma::store_matrix_sync(p, acc[i][j], 128, wmma::mem_row_major);
        }
}

// ================= K2: fused middle chain (warp-per-row) =================
#define W2T_OFF   0
#define W3T_OFF   (W2T_OFF + 128*64)
#define W4S_OFF   (W3T_OFF + 64*32)
#define DW1T_OFF  (W4S_OFF + 96)
#define DW2T_OFF  (DW1T_OFF + 96)
#define DW3T_OFF  (DW2T_OFF + 32*64)
#define EB1_OFF   (DW3T_OFF + 64*128)
#define EB2_OFF   (EB1_OFF + 128)
#define EB3_OFF   (EB2_OFF + 64)
#define EB4_OFF   (EB3_OFF + 32)
#define DB1_OFF   (EB4_OFF + 4)
#define DB2_OFF   (DB1_OFF + 32)
#define DB3_OFF   (DB2_OFF + 64)
#define W1L_OFF   (DB3_OFF + 128)
#define COEF_OFF  (W1L_OFF + 128)
#define BUF_OFF   (COEF_OFF + 24)
#define LRED_OFF  (BUF_OFF + 8*256)
#define K2_FLOATS (LRED_OFF + 24)
#define K2_SMEM   (K2_FLOATS * 4)

__device__ __forceinline__ float sigf(float x) { return 1.f/(1.f+__expf(-x)); }

__global__ void __launch_bounds__(256) k2_chain(
    const float* __restrict__ treatment, const float* __restrict__ size_,
    const float* __restrict__ eW1, const float* __restrict__ eb1,
    const float* __restrict__ eW2, const float* __restrict__ eb2,
    const float* __restrict__ eW3, const float* __restrict__ eb3,
    const float* __restrict__ eW4, const float* __restrict__ eb4,
    const float* __restrict__ dW1, const float* __restrict__ db1,
    const float* __restrict__ dW2, const float* __restrict__ db2,
    const float* __restrict__ dW3, const float* __restrict__ db3,
    const float* __restrict__ coef,
    float* __restrict__ out)
{
    extern __shared__ float sm[];
    const int tid = threadIdx.x;

    for (int i = tid; i < 64*128; i += 256) { int n=i>>7, k=i&127; sm[W2T_OFF + k*64 + n] = eW2[i]; }
    for (int i = tid; i < 32*64;  i += 256) { int n=i>>6, k=i&63;  sm[W3T_OFF + k*32 + n] = eW3[i]; }
    for (int i = tid; i < 3*32;   i += 256) sm[W4S_OFF + i] = eW4[i];
    for (int i = tid; i < 32*3;   i += 256) { int n=i/3,  k=i%3;  sm[DW1T_OFF + k*32 + n] = dW1[i]; }
    for (int i = tid; i < 64*32;  i += 256) { int n=i>>5, k=i&31; sm[DW2T_OFF + k*64 + n] = dW2[i]; }
    for (int i = tid; i < 128*64; i += 256) { int n=i>>6, k=i&63; sm[DW3T_OFF + k*128 + n] = dW3[i]; }
    if (tid < 128) sm[EB1_OFF+tid] = eb1[tid];
    if (tid < 64)  sm[EB2_OFF+tid] = eb2[tid];
    if (tid < 32)  sm[EB3_OFF+tid] = eb3[tid];
    if (tid < 3)   sm[EB4_OFF+tid] = eb4[tid];
    if (tid < 32)  sm[DB1_OFF+tid] = db1[tid];
    if (tid < 64)  sm[DB2_OFF+tid] = db2[tid];
    if (tid < 128) sm[DB3_OFF+tid] = db3[tid];
    if (tid < 128) sm[W1L_OFF+tid] = eW1[tid*2049 + 2048];
    if (tid < 21)  sm[COEF_OFF+tid] = coef[tid];
    __syncthreads();

    const int w = tid >> 5, lane = tid & 31;
    float* abuf = sm + BUF_OFF + w*256;
    float* dbuf = abuf + 128;
    float po = 0.f, tr = 0.f, szl = 0.f;

    for (int rr = 0; rr < 4; rr++) {
        const int row = (blockIdx.x*8 + w)*4 + rr;
        const float tre = treatment[row];

        #pragma unroll
        for (int jj=0;jj<4;jj++) {
            int n = lane + 32*jj;
            float add = tre * sm[W1L_OFF+n];
            float a1  = sigf(g_prea[(long)row*128+n] + add + sm[EB1_OFF+n]);
            float pd  = g_pred[(long)row*128+n] + add;
            abuf[n] = a1;
            dbuf[n] = a1*(1.f-a1)*pd;
        }
        __syncwarp();
        float a2v[2], d2v[2];
        #pragma unroll
        for (int jj=0;jj<2;jj++) {
            int n = lane + 32*jj;
            float s1 = sm[EB2_OFF+n], s2 = 0.f;
            #pragma unroll 8
            for (int k=0;k<128;k++) {
                float wv = sm[W2T_OFF + k*64 + n];
                s1 = fmaf(abuf[k], wv, s1);
                s2 = fmaf(dbuf[k], wv, s2);
            }
            float a = sigf(s1);
            a2v[jj] = a; d2v[jj] = a*(1.f-a)*s2;
        }
        __syncwarp();
        abuf[lane]=a2v[0]; abuf[lane+32]=a2v[1];
        dbuf[lane]=d2v[0]; dbuf[lane+32]=d2v[1];
        __syncwarp();
        {
            float s1 = sm[EB3_OFF+lane], s2 = 0.f;
            #pragma unroll 8
            for (int k=0;k<64;k++) {
                float wv = sm[W3T_OFF + k*32 + lane];
                s1 = fmaf(abuf[k], wv, s1);
                s2 = fmaf(dbuf[k], wv, s2);
            }
            float a = sigf(s1);
            float d = a*(1.f-a)*s2;
            __syncwarp();
            abuf[lane] = a; dbuf[lane] = d;
        }
        __syncwarp();
        float zz[3], zt[3];
        #pragma unroll
        for (int j=0;j<3;j++) {
            float s1 = sm[EB4_OFF+j], s2 = 0.f;
            #pragma unroll
            for (int k=0;k<32;k++) {
                float wv = sm[W4S_OFF + j*32 + k];
                s1 = fmaf(abuf[k], wv, s1);
                s2 = fmaf(dbuf[k], wv, s2);
            }
            zz[j]=s1; zt[j]=s2;
        }
        const float s = zz[0], d = zz[1], t3 = zz[2];
        float th[7] = {1.f, s, s*s, s*d, s*t3, s*s*d, s*s*t3};
        float zp[3] = {0.f,0.f,0.f};
        #pragma unroll
        for (int i=0;i<7;i++) {
            zp[0] = fmaf(th[i], sm[COEF_OFF+i*3+0], zp[0]);
            zp[1] = fmaf(th[i], sm[COEF_OFF+i*3+1], zp[1]);
            zp[2] = fmaf(th[i], sm[COEF_OFF+i*3+2], zp[2]);
        }
        if (lane == 0) {
            float dpo = s - size_[row];
            po += dpo*dpo;
            float l = t3;
            tr += fmaxf(l, 0.f) + log1pf(expf(-fabsf(l))) - l*tre;
            float e0 = zt[0]-zp[0], e1 = zt[1]-zp[1], e2 = zt[2]-zp[2];
            szl += e0*e0 + e1*e1 + e2*e2;
        }
        if (lane < 3) out[(long)row*3 + lane] = zz[lane];
        __syncwarp();
        {
            float w0 = sm[DW1T_OFF + 0*32 + lane];
            float w1 = sm[DW1T_OFF + 1*32 + lane];
            float w2 = sm[DW1T_OFF + 2*32 + lane];
            float h  = sigf(sm[DB1_OFF+lane] + s*w0 + d*w1 + t3*w2);
            float pd = zp[0]*w0 + zp[1]*w1 + zp[2]*w2;
            abuf[lane] = h; dbuf[lane] = h*(1.f-h)*pd;
        }
        __syncwarp();
        float h2v[2], dd2v[2];
        #pragma unroll
        for (int jj=0;jj<2;jj++) {
            int n = lane + 32*jj;
            float s1 = sm[DB2_OFF+n], s2 = 0.f;
            #pragma unroll
            for (int k=0;k<32;k++) {
                float wv = sm[DW2T_OFF + k*64 + n];
                s1 = fmaf(abuf[k], wv, s1);
                s2 = fmaf(dbuf[k], wv, s2);
            }
            float h = sigf(s1);
            h2v[jj]=h; dd2v[jj]=h*(1.f-h)*s2;
        }
        __syncwarp();
        abuf[lane]=h2v[0]; abuf[lane+32]=h2v[1];
        dbuf[lane]=dd2v[0]; dbuf[lane+32]=dd2v[1];
        __syncwarp();
        #pragma unroll
        for (int jj=0;jj<4;jj++) {
            int n = lane + 32*jj;
            float s1 = sm[DB3_OFF+n], s2 = 0.f;
            #pragma unroll 8
            for (int k=0;k<64;k++) {
                float wv = sm[DW3T_OFF + k*128 + n];
                s1 = fmaf(abuf[k], wv, s1);
                s2 = fmaf(dbuf[k], wv, s2);
            }
            float h = sigf(s1);
            float hd = h*(1.f-h)*s2;
            long idx = (long)row*128 + n;
            __nv_bfloat16 hh, hl;
            split2(h, hh, hl);
            g_h3h[idx] = hh;
            g_h3l[idx] = hl;
            g_d3h[idx] = __float2bfloat16(hd);
        }
        __syncwarp();
    }
    if (lane == 0) {
        sm[LRED_OFF + w]      = po;
        sm[LRED_OFF + 8 + w]  = tr;
        sm[LRED_OFF + 16 + w] = szl;
    }
    __syncthreads();
    if (tid == 0) {
        float a=0.f,b=0.f,c=0.f;
        for (int i=0;i<8;i++){ a+=sm[LRED_OFF+i]; b+=sm[LRED_OFF+8+i]; c+=sm[LRED_OFF+16+i]; }
        g_part_po[blockIdx.x]=a; g_part_tr[blockIdx.x]=b; g_part_sz[blockIdx.x]=c;
    }
}

// ================= K3: GEMM (M=16384, N=2048, K=128), pipelined cp.async ====
__global__ void __launch_bounds__(256, 2) k3_gemm(
    const float* __restrict__ db4,
    const float* __restrict__ x, const float* __restrict__ x_dot,
    float* __restrict__ out)
{
    extern __shared__ __nv_bfloat16 smb[];
    __shared__ float red[256];
    float* smf = reinterpret_cast<float*>(smb);

    const int path = blockIdx.z;
    const __nv_bfloat16* Ahg16 = (path == 0) ? g_h3h : g_d3h;
    const uint4* Ahg = reinterpret_cast<const uint4*>(Ahg16);
    const uint4* Alg = reinterpret_cast<const uint4*>(g_h3l);
    const uint4* Bhg = reinterpret_cast<const uint4*>(g_dW4h);
    const uint4* Blg = reinterpret_cast<const uint4*>(g_dW4l);

    const int m0 = blockIdx.y * 128;
    const int n0 = blockIdx.x * 128;
    const int tid = threadIdx.x;
    const int w  = tid >> 5;
    const int wr = w >> 2;
    const int wc = w & 3;
    const int cr  = tid >> 2;    // rows 0..63 (+64)
    const int cgc = tid & 3;

    wmma::fragment<wmma::accumulator,16,16,16,float> acc[4][2];
    #pragma unroll
    for (int i=0;i<4;i++)
        #pragma unroll
        for(int j=0;j<2;j++) wmma::fill_fragment(acc[i][j], 0.0f);

    // prefetch chunk 0 into stage 0
    {
        __nv_bfloat16* Ah = smb;
        __nv_bfloat16* Al = smb + STAGE_BF16;
        __nv_bfloat16* Bh = smb + 2*STAGE_BF16;
        __nv_bfloat16* Bl = smb + 3*STAGE_BF16;
        #pragma unroll
        for (int i=0;i<2;i++) {
            int r = cr + 64*i;
            cpa16(&Ah[r*TS2 + cgc*8], &Ahg[(long)(m0+r)*16 + cgc]);
            cpa16(&Bh[r*TS2 + cgc*8], &Bhg[(n0+r)*16 + cgc]);
            if (path == 0) {
                cpa16(&Al[r*TS2 + cgc*8], &Alg[(long)(m0+r)*16 + cgc]);
                cpa16(&Bl[r*TS2 + cgc*8], &Blg[(n0+r)*16 + cgc]);
            }
        }
        cp_commit();
    }

    #pragma unroll 1
    for (int c = 0; c < 4; c++) {
        const int s  = c & 1;
        const int sn = s ^ 1;
        if (c < 3) {
            __nv_bfloat16* Ah = smb + sn*4*STAGE_BF16;
            __nv_bfloat16* Al = Ah + STAGE_BF16;
            __nv_bfloat16* Bh = Ah + 2*STAGE_BF16;
            __nv_bfloat16* Bl = Ah + 3*STAGE_BF16;
            #pragma unroll
            for (int i=0;i<2;i++) {
                int r = cr + 64*i;
                cpa16(&Ah[r*TS2 + cgc*8], &Ahg[(long)(m0+r)*16 + (c+1)*4 + cgc]);
                cpa16(&Bh[r*TS2 + cgc*8], &Bhg[(n0+r)*16 + (c+1)*4 + cgc]);
                if (path == 0) {
                    cpa16(&Al[r*TS2 + cgc*8], &Alg[(long)(m0+r)*16 + (c+1)*4 + cgc]);
                    cpa16(&Bl[r*TS2 + cgc*8], &Blg[(n0+r)*16 + (c+1)*4 + cgc]);
                }
            }
            cp_commit();
            cp_wait1();
        } else {
            cp_wait0();
        }
        __syncthreads();
        {
            __nv_bfloat16* Ah = smb + s*4*STAGE_BF16;
            __nv_bfloat16* Al = Ah + STAGE_BF16;
            __nv_bfloat16* Bh = Ah + 2*STAGE_BF16;
            __nv_bfloat16* Bl = Ah + 3*STAGE_BF16;
            #pragma unroll
            for (int kk = 0; kk < 32; kk += 16) {
                wmma::fragment<wmma::matrix_b,16,16,16,__nv_bfloat16,wmma::col_major> bh[2], bl[2];
                #pragma unroll
                for (int j=0;j<2;j++) {
                    wmma::load_matrix_sync(bh[j], &Bh[(wc*32 + j*16)*TS2 + kk], TS2);
                    if (path == 0)
                        wmma::load_matrix_sync(bl[j], &Bl[(wc*32 + j*16)*TS2 + kk], TS2);
                }
                #pragma unroll
                for (int i=0;i<4;i++) {
                    wmma::fragment<wmma::matrix_a,16,16,16,__nv_bfloat16,wmma::row_major> ah, al;
                    wmma::load_matrix_sync(ah, &Ah[(wr*64 + i*16)*TS2 + kk], TS2);
                    if (path == 0)
                        wmma::load_matrix_sync(al, &Al[(wr*64 + i*16)*TS2 + kk], TS2);
                    #pragma unroll
                    for (int j=0;j<2;j++) {
                        wmma::mma_sync(acc[i][j], ah, bh[j], acc[i][j]);
                        if (path == 0) {
                            wmma::mma_sync(acc[i][j], al, bh[j], acc[i][j]);
                            wmma::mma_sync(acc[i][j], ah, bl[j], acc[i][j]);
                        }
                    }
                }
            }
        }
        __syncthreads();
    }
    // epilogue: per-warp staging, fused bias+store+loss
    float lacc = 0.f;
    float* stage = smf + w * 336;
    #pragma unroll
    for (int i=0;i<4;i++) {
        #pragma unroll
        for (int j=0;j<2;j++) {
            wmma::store_matrix_sync(stage, acc[i][j], 20, wmma::mem_row_major);
            __syncwarp();
            const int mbase = m0 + wr*64 + i*16;
            const int nbase = n0 + wc*32 + j*16;
            #pragma unroll
            for (int q=0;q<8;q++) {
                int e = (tid & 31) + 32*q;
                int r = e >> 4, c = e & 15;
                float v = stage[r*20 + c];
                long m = mbase + r; long n = nbase + c;
                if (path == 0) {
                    v += db4[n];
                    out[XHAT_OFF + m*2048 + n] = v;
                    float df = v - x[m*2048 + n];
                    lacc += df*df;
                } else {
                    float df = v - x_dot[m*2048 + n];
                    lacc += df*df;
                }
            }
            __syncwarp();
        }
    }
    red[tid] = lacc;
    __syncthreads();
    for (int sft = 128; sft > 0; sft >>= 1) {
        if (tid < sft) red[tid] += red[tid + sft];
        __syncthreads();
    }
    if (tid == 0) {
        int idx = blockIdx.y*16 + blockIdx.x;
        if (path == 0) g_part_rec[idx] = red[0];
        else           g_part_sx[idx]  = red[0];
    }
}

// ================= K4: deterministic finalize =================
__global__ void k4_final(const float* __restrict__ coef, float* __restrict__ out) {
    const int w = threadIdx.x >> 5, lane = threadIdx.x & 31;
    float s = 0.f;
    if      (w == 0) { for (int i=lane;i<512;i+=32)  s += g_part_po[i]; }
    else if (w == 1) { for (int i=lane;i<512;i+=32)  s += g_part_tr[i]; }
    else if (w == 2) { for (int i=lane;i<512;i+=32)  s += g_part_sz[i]; }
    else if (w == 3) { for (int i=lane;i<2048;i+=32) s += g_part_rec[i]; }
    else if (w == 4) { for (int i=lane;i<2048;i+=32) s += g_part_sx[i]; }
    else             { for (int i=lane;i<21;i+=32)   s += fabsf(coef[i]); }
    #pragma unroll
    for (int o=16;o>0;o>>=1) s += __shfl_down_sync(0xffffffffu, s, o);
    if (lane == 0) {
        if      (w == 0) out[SCAL_OFF+0] = s / 16384.f;
        else if (w == 1) out[SCAL_OFF+1] = s / 16384.f;
        else if (w == 2) out[SCAL_OFF+4] = s / (16384.f*3.f);
        else if (w == 3) out[SCAL_OFF+2] = s / (16384.f*2048.f);
        else if (w == 4) out[SCAL_OFF+3] = s / (16384.f*2048.f);
        else             out[SCAL_OFF+5] = s / 21.f;
    }
}

// ================= launch =================
extern "C" void kernel_launch(void* const* d_in, const int* in_sizes, int n_in,
                              void* d_out, int out_size) {
    const float* x         = (const float*)d_in[0];
    const float* x_dot     = (const float*)d_in[1];
    const float* treatment = (const float*)d_in[2];
    const float* size_     = (const float*)d_in[3];
    const float* eW1 = (const float*)d_in[4];  const float* eb1 = (const float*)d_in[5];
    const float* eW2 = (const float*)d_in[6];  const float* eb2 = (const float*)d_in[7];
    const float* eW3 = (const float*)d_in[8];  const float* eb3 = (const float*)d_in[9];
    const float* eW4 = (const float*)d_in[10]; const float* eb4 = (const float*)d_in[11];
    const float* dW1 = (const float*)d_in[12]; const float* db1 = (const float*)d_in[13];
    const float* dW2 = (const float*)d_in[14]; const float* db2 = (const float*)d_in[15];
    const float* dW3 = (const float*)d_in[16]; const float* db3 = (const float*)d_in[17];
    const float* dW4 = (const float*)d_in[18]; const float* db4 = (const float*)d_in[19];
    const float* coef = (const float*)d_in[20];
    float* out = (float*)d_out;

    cudaFuncSetAttribute(k1_gemm, cudaFuncAttributeMaxDynamicSharedMemorySize, GEMM_SMEM);
    cudaFuncSetAttribute(k3_gemm, cudaFuncAttributeMaxDynamicSharedMemorySize, GEMM_SMEM);
    cudaFuncSetAttribute(k2_chain, cudaFuncAttributeMaxDynamicSharedMemorySize, K2_SMEM);

    k0_prep<<<1024, 256>>>(eW1, dW4);
    k1_gemm<<<dim3(128, 2), 256, GEMM_SMEM>>>(x, x_dot);
    k2_chain<<<512, 256, K2_SMEM>>>(treatment, size_, eW1, eb1, eW2, eb2, eW3, eb3,
                                    eW4, eb4, dW1, db1, dW2, db2, dW3, db3, coef, out);
    k3_gemm<<<dim3(16, 128, 2), 256, GEMM_SMEM>>>(db4, x, x_dot, out);
    k4_final<<<1, 192>>>(coef, out);
}

// round 5
// speedup vs baseline: 3.2547x; 1.2974x over previous
#include <cuda_runtime.h>
#include <cuda_fp16.h>
#include <mma.h>
#include <cstdint>

using namespace nvcuda;

#define B_SZ   16384
#define DIN    2048
#define XHAT_OFF (16384L*3)
#define SCAL_OFF (16384L*3 + 16384L*2048)
#define TS2 40                       // fp16 smem row stride (80B; conflict-free ldmatrix)
#define STAGE_H (128*TS2)            // one 128x32 tile (padded), in halves
#define K1_SMEM (2*3*STAGE_H*2)      // 2 stages * 3 arrays (Ah,Al,Bh) = 61440 B
#define K3_SMEM (2*3*STAGE_H*2)

// ---------------- scratch (device globals; no allocation allowed) ----------------
__device__ float g_prea[B_SZ*128];
__device__ float g_pred[B_SZ*128];
__device__ __align__(256) __half g_h3h[B_SZ*128];
__device__ __align__(256) __half g_h3l[B_SZ*128];
__device__ __align__(256) __half g_d3h[B_SZ*128];
__device__ __align__(256) __half g_eW1h[128*2048];
__device__ __align__(256) __half g_dW4h[2048*128];
__device__ float g_part_po[512], g_part_tr[512], g_part_sz[512];
__device__ float g_part_rec[2048], g_part_sx[2048];

__device__ __forceinline__ void split2h(float v, __half& h, __half& l) {
    h = __float2half(v);
    l = __float2half(v - __half2float(h));
}
__device__ __forceinline__ unsigned pkh(__half a, __half b) {
    __half2 t = __halves2half2(a, b);
    return *reinterpret_cast<unsigned*>(&t);
}
__device__ __forceinline__ void cpa16(void* sdst, const void* gsrc) {
    unsigned s = (unsigned)__cvta_generic_to_shared(sdst);
    asm volatile("cp.async.cg.shared.global [%0], [%1], 16;\n" :: "r"(s), "l"(gsrc));
}
__device__ __forceinline__ void cp_commit() { asm volatile("cp.async.commit_group;\n"); }
__device__ __forceinline__ void cp_wait1() { asm volatile("cp.async.wait_group 1;\n"); }
__device__ __forceinline__ void cp_wait0() { asm volatile("cp.async.wait_group 0;\n"); }

// ================= K0: pre-round weights to fp16 =================
__global__ void __launch_bounds__(256) k0_prep(const float* __restrict__ eW1,
                                               const float* __restrict__ dW4) {
    int i = blockIdx.x * 256 + threadIdx.x;
    if (i < 128*2048) {
        int n = i >> 11, k = i & 2047;
        g_eW1h[i] = __float2half(eW1[n*2049 + k]);
    }
    if (i < 2048*128) {
        g_dW4h[i] = __float2half(dW4[i]);
    }
}

// ================= K1: GEMM (M=16384, N=128, K=2048) fp16, pipelined =================
// path 0 (x): 2-pass AhBh + AlBh; path 1 (x_dot): 1-pass AhBh (scalar losses only)
__global__ void __launch_bounds__(256, 2) k1_gemm(
    const float* __restrict__ x, const float* __restrict__ x_dot)
{
    extern __shared__ __half smb[];
    const int path = blockIdx.y;
    const float* A = (path == 0) ? x : x_dot;
    float* Out = (path == 0) ? g_prea : g_pred;
    const int m0 = blockIdx.x * 128;
    const int tid = threadIdx.x;
    const int w  = tid >> 5;
    const int wr = w >> 2;
    const int wc = w & 3;

    const float4* Asrc = reinterpret_cast<const float4*>(A);
    const uint4*  Bhg  = reinterpret_cast<const uint4*>(g_eW1h);

    const int ar  = tid >> 3;
    const int ac4 = tid & 7;
    const int br  = tid >> 2;
    const int bgc = tid & 3;

    wmma::fragment<wmma::accumulator,16,16,16,float> acc[4][2];
    #pragma unroll
    for (int i=0;i<4;i++)
        #pragma unroll
        for(int j=0;j<2;j++) wmma::fill_fragment(acc[i][j], 0.0f);

    float4 areg[4];
    #pragma unroll
    for (int i=0;i<4;i++)
        areg[i] = Asrc[(long)(m0 + ar + 32*i)*512 + ac4];
    {
        __half* Bh = smb + 2*STAGE_H;
        #pragma unroll
        for (int i=0;i<2;i++) {
            int r = br + 64*i;
            cpa16(&Bh[r*TS2 + bgc*8], &Bhg[r*256 + bgc]);
        }
        cp_commit();
        __half* Ah = smb;
        __half* Al = smb + STAGE_H;
        #pragma unroll
        for (int i=0;i<4;i++) {
            int r = ar + 32*i;
            float4 v = areg[i];
            __half h0,h1,h2,h3,l0,l1,l2,l3;
            split2h(v.x,h0,l0); split2h(v.y,h1,l1); split2h(v.z,h2,l2); split2h(v.w,h3,l3);
            unsigned* ph = reinterpret_cast<unsigned*>(&Ah[r*TS2 + ac4*4]);
            ph[0]=pkh(h0,h1); ph[1]=pkh(h2,h3);
            if (path == 0) {
                unsigned* pl = reinterpret_cast<unsigned*>(&Al[r*TS2 + ac4*4]);
                pl[0]=pkh(l0,l1); pl[1]=pkh(l2,l3);
            }
        }
    }

    #pragma unroll 1
    for (int c = 0; c < 64; c++) {
        const int s  = c & 1;
        const int sn = s ^ 1;
        if (c < 63) {
            #pragma unroll
            for (int i=0;i<4;i++)
                areg[i] = Asrc[(long)(m0 + ar + 32*i)*512 + (c+1)*8 + ac4];
            __half* Bh = smb + sn*3*STAGE_H + 2*STAGE_H;
            #pragma unroll
            for (int i=0;i<2;i++) {
                int r = br + 64*i;
                cpa16(&Bh[r*TS2 + bgc*8], &Bhg[r*256 + (c+1)*4 + bgc]);
            }
            cp_commit();
            cp_wait1();
        } else {
            cp_wait0();
        }
        __syncthreads();
        {
            __half* Ah = smb + s*3*STAGE_H;
            __half* Al = Ah + STAGE_H;
            __half* Bh = Ah + 2*STAGE_H;
            #pragma unroll
            for (int kk = 0; kk < 32; kk += 16) {
                wmma::fragment<wmma::matrix_b,16,16,16,__half,wmma::col_major> bh[2];
                #pragma unroll
                for (int j=0;j<2;j++)
                    wmma::load_matrix_sync(bh[j], &Bh[(wc*32 + j*16)*TS2 + kk], TS2);
                #pragma unroll
                for (int i=0;i<4;i++) {
                    wmma::fragment<wmma::matrix_a,16,16,16,__half,wmma::row_major> ah;
                    wmma::load_matrix_sync(ah, &Ah[(wr*64 + i*16)*TS2 + kk], TS2);
                    #pragma unroll
                    for (int j=0;j<2;j++)
                        wmma::mma_sync(acc[i][j], ah, bh[j], acc[i][j]);
                    if (path == 0) {
                        wmma::fragment<wmma::matrix_a,16,16,16,__half,wmma::row_major> al;
                        wmma::load_matrix_sync(al, &Al[(wr*64 + i*16)*TS2 + kk], TS2);
                        #pragma unroll
                        for (int j=0;j<2;j++)
                            wmma::mma_sync(acc[i][j], al, bh[j], acc[i][j]);
                    }
                }
            }
        }
        if (c < 63) {
            __syncthreads();
            __half* Ah = smb + sn*3*STAGE_H;
            __half* Al = Ah + STAGE_H;
            #pragma unroll
            for (int i=0;i<4;i++) {
                int r = ar + 32*i;
                float4 v = areg[i];
                __half h0,h1,h2,h3,l0,l1,l2,l3;
                split2h(v.x,h0,l0); split2h(v.y,h1,l1); split2h(v.z,h2,l2); split2h(v.w,h3,l3);
                unsigned* ph = reinterpret_cast<unsigned*>(&Ah[r*TS2 + ac4*4]);
                ph[0]=pkh(h0,h1); ph[1]=pkh(h2,h3);
                if (path == 0) {
                    unsigned* pl = reinterpret_cast<unsigned*>(&Al[r*TS2 + ac4*4]);
                    pl[0]=pkh(l0,l1); pl[1]=pkh(l2,l3);
                }
            }
        }
    }
    #pragma unroll
    for (int i=0;i<4;i++)
        #pragma unroll
        for (int j=0;j<2;j++) {
            float* p = Out + (long)(m0 + wr*64 + i*16)*128 + wc*32 + j*16;
            wmma::store_matrix_sync(p, acc[i][j], 128, wmma::mem_row_major);
        }
}

// ================= K2: fused middle chain (warp-per-row) =================
#define W2T_OFF   0
#define W3T_OFF   (W2T_OFF + 128*64)
#define W4S_OFF   (W3T_OFF + 64*32)
#define DW1T_OFF  (W4S_OFF + 96)
#define DW2T_OFF  (DW1T_OFF + 96)
#define DW3T_OFF  (DW2T_OFF + 32*64)
#define EB1_OFF   (DW3T_OFF + 64*128)
#define EB2_OFF   (EB1_OFF + 128)
#define EB3_OFF   (EB2_OFF + 64)
#define EB4_OFF   (EB3_OFF + 32)
#define DB1_OFF   (EB4_OFF + 4)
#define DB2_OFF   (DB1_OFF + 32)
#define DB3_OFF   (DB2_OFF + 64)
#define W1L_OFF   (DB3_OFF + 128)
#define COEF_OFF  (W1L_OFF + 128)
#define BUF_OFF   (COEF_OFF + 24)
#define LRED_OFF  (BUF_OFF + 8*256)
#define K2_FLOATS (LRED_OFF + 24)
#define K2_SMEM   (K2_FLOATS * 4)

__device__ __forceinline__ float sigf(float x) { return 1.f/(1.f+__expf(-x)); }

__global__ void __launch_bounds__(256) k2_chain(
    const float* __restrict__ treatment, const float* __restrict__ size_,
    const float* __restrict__ eW1, const float* __restrict__ eb1,
    const float* __restrict__ eW2, const float* __restrict__ eb2,
    const float* __restrict__ eW3, const float* __restrict__ eb3,
    const float* __restrict__ eW4, const float* __restrict__ eb4,
    const float* __restrict__ dW1, const float* __restrict__ db1,
    const float* __restrict__ dW2, const float* __restrict__ db2,
    const float* __restrict__ dW3, const float* __restrict__ db3,
    const float* __restrict__ coef,
    float* __restrict__ out)
{
    extern __shared__ float sm[];
    const int tid = threadIdx.x;

    for (int i = tid; i < 64*128; i += 256) { int n=i>>7, k=i&127; sm[W2T_OFF + k*64 + n] = eW2[i]; }
    for (int i = tid; i < 32*64;  i += 256) { int n=i>>6, k=i&63;  sm[W3T_OFF + k*32 + n] = eW3[i]; }
    for (int i = tid; i < 3*32;   i += 256) sm[W4S_OFF + i] = eW4[i];
    for (int i = tid; i < 32*3;   i += 256) { int n=i/3,  k=i%3;  sm[DW1T_OFF + k*32 + n] = dW1[i]; }
    for (int i = tid; i < 64*32;  i += 256) { int n=i>>5, k=i&31; sm[DW2T_OFF + k*64 + n] = dW2[i]; }
    for (int i = tid; i < 128*64; i += 256) { int n=i>>6, k=i&63; sm[DW3T_OFF + k*128 + n] = dW3[i]; }
    if (tid < 128) sm[EB1_OFF+tid] = eb1[tid];
    if (tid < 64)  sm[EB2_OFF+tid] = eb2[tid];
    if (tid < 32)  sm[EB3_OFF+tid] = eb3[tid];
    if (tid < 3)   sm[EB4_OFF+tid] = eb4[tid];
    if (tid < 32)  sm[DB1_OFF+tid] = db1[tid];
    if (tid < 64)  sm[DB2_OFF+tid] = db2[tid];
    if (tid < 128) sm[DB3_OFF+tid] = db3[tid];
    if (tid < 128) sm[W1L_OFF+tid] = eW1[tid*2049 + 2048];
    if (tid < 21)  sm[COEF_OFF+tid] = coef[tid];
    __syncthreads();

    const int w = tid >> 5, lane = tid & 31;
    float* abuf = sm + BUF_OFF + w*256;
    float* dbuf = abuf + 128;
    float po = 0.f, tr = 0.f, szl = 0.f;

    for (int rr = 0; rr < 4; rr++) {
        const int row = (blockIdx.x*8 + w)*4 + rr;
        const float tre = treatment[row];

        #pragma unroll
        for (int jj=0;jj<4;jj++) {
            int n = lane + 32*jj;
            float add = tre * sm[W1L_OFF+n];
            float a1  = sigf(g_prea[(long)row*128+n] + add + sm[EB1_OFF+n]);
            float pd  = g_pred[(long)row*128+n] + add;
            abuf[n] = a1;
            dbuf[n] = a1*(1.f-a1)*pd;
        }
        __syncwarp();
        float a2v[2], d2v[2];
        #pragma unroll
        for (int jj=0;jj<2;jj++) {
            int n = lane + 32*jj;
            float s1 = sm[EB2_OFF+n], s2 = 0.f;
            #pragma unroll 8
            for (int k=0;k<128;k++) {
                float wv = sm[W2T_OFF + k*64 + n];
                s1 = fmaf(abuf[k], wv, s1);
                s2 = fmaf(dbuf[k], wv, s2);
            }
            float a = sigf(s1);
            a2v[jj] = a; d2v[jj] = a*(1.f-a)*s2;
        }
        __syncwarp();
        abuf[lane]=a2v[0]; abuf[lane+32]=a2v[1];
        dbuf[lane]=d2v[0]; dbuf[lane+32]=d2v[1];
        __syncwarp();
        {
            float s1 = sm[EB3_OFF+lane], s2 = 0.f;
            #pragma unroll 8
            for (int k=0;k<64;k++) {
                float wv = sm[W3T_OFF + k*32 + lane];
                s1 = fmaf(abuf[k], wv, s1);
                s2 = fmaf(dbuf[k], wv, s2);
            }
            float a = sigf(s1);
            float d = a*(1.f-a)*s2;
            __syncwarp();
            abuf[lane] = a; dbuf[lane] = d;
        }
        __syncwarp();
        float zz[3], zt[3];
        #pragma unroll
        for (int j=0;j<3;j++) {
            float s1 = sm[EB4_OFF+j], s2 = 0.f;
            #pragma unroll
            for (int k=0;k<32;k++) {
                float wv = sm[W4S_OFF + j*32 + k];
                s1 = fmaf(abuf[k], wv, s1);
                s2 = fmaf(dbuf[k], wv, s2);
            }
            zz[j]=s1; zt[j]=s2;
        }
        const float s = zz[0], d = zz[1], t3 = zz[2];
        float th[7] = {1.f, s, s*s, s*d, s*t3, s*s*d, s*s*t3};
        float zp[3] = {0.f,0.f,0.f};
        #pragma unroll
        for (int i=0;i<7;i++) {
            zp[0] = fmaf(th[i], sm[COEF_OFF+i*3+0], zp[0]);
            zp[1] = fmaf(th[i], sm[COEF_OFF+i*3+1], zp[1]);
            zp[2] = fmaf(th[i], sm[COEF_OFF+i*3+2], zp[2]);
        }
        if (lane == 0) {
            float dpo = s - size_[row];
            po += dpo*dpo;
            float l = t3;
            tr += fmaxf(l, 0.f) + log1pf(expf(-fabsf(l))) - l*tre;
            float e0 = zt[0]-zp[0], e1 = zt[1]-zp[1], e2 = zt[2]-zp[2];
            szl += e0*e0 + e1*e1 + e2*e2;
        }
        if (lane < 3) out[(long)row*3 + lane] = zz[lane];
        __syncwarp();
        {
            float w0 = sm[DW1T_OFF + 0*32 + lane];
            float w1 = sm[DW1T_OFF + 1*32 + lane];
            float w2 = sm[DW1T_OFF + 2*32 + lane];
            float h  = sigf(sm[DB1_OFF+lane] + s*w0 + d*w1 + t3*w2);
            float pd = zp[0]*w0 + zp[1]*w1 + zp[2]*w2;
            abuf[lane] = h; dbuf[lane] = h*(1.f-h)*pd;
        }
        __syncwarp();
        float h2v[2], dd2v[2];
        #pragma unroll
        for (int jj=0;jj<2;jj++) {
            int n = lane + 32*jj;
            float s1 = sm[DB2_OFF+n], s2 = 0.f;
            #pragma unroll
            for (int k=0;k<32;k++) {
                float wv = sm[DW2T_OFF + k*64 + n];
                s1 = fmaf(abuf[k], wv, s1);
                s2 = fmaf(dbuf[k], wv, s2);
            }
            float h = sigf(s1);
            h2v[jj]=h; dd2v[jj]=h*(1.f-h)*s2;
        }
        __syncwarp();
        abuf[lane]=h2v[0]; abuf[lane+32]=h2v[1];
        dbuf[lane]=dd2v[0]; dbuf[lane+32]=dd2v[1];
        __syncwarp();
        #pragma unroll
        for (int jj=0;jj<4;jj++) {
            int n = lane + 32*jj;
            float s1 = sm[DB3_OFF+n], s2 = 0.f;
            #pragma unroll 8
            for (int k=0;k<64;k++) {
                float wv = sm[DW3T_OFF + k*128 + n];
                s1 = fmaf(abuf[k], wv, s1);
                s2 = fmaf(dbuf[k], wv, s2);
            }
            float h = sigf(s1);
            float hd = h*(1.f-h)*s2;
            long idx = (long)row*128 + n;
            __half hh, hl;
            split2h(h, hh, hl);
            g_h3h[idx] = hh;
            g_h3l[idx] = hl;
            g_d3h[idx] = __float2half(hd);
        }
        __syncwarp();
    }
    if (lane == 0) {
        sm[LRED_OFF + w]      = po;
        sm[LRED_OFF + 8 + w]  = tr;
        sm[LRED_OFF + 16 + w] = szl;
    }
    __syncthreads();
    if (tid == 0) {
        float a=0.f,b=0.f,c=0.f;
        for (int i=0;i<8;i++){ a+=sm[LRED_OFF+i]; b+=sm[LRED_OFF+8+i]; c+=sm[LRED_OFF+16+i]; }
        g_part_po[blockIdx.x]=a; g_part_tr[blockIdx.x]=b; g_part_sz[blockIdx.x]=c;
    }
}

// ================= K3: GEMM (M=16384, N=2048, K=128), pipelined cp.async ====
// path 0: x_hat = h3 @ dW4.T + db4 (2-pass AhBh+AlBh); path 1: 1-pass (scalar loss)
__global__ void __launch_bounds__(256, 2) k3_gemm(
    const float* __restrict__ db4,
    const float* __restrict__ x, const float* __restrict__ x_dot,
    float* __restrict__ out)
{
    extern __shared__ __half smb[];
    __shared__ float red[256];
    float* smf = reinterpret_cast<float*>(smb);

    const int path = blockIdx.z;
    const __half* Ahg16 = (path == 0) ? g_h3h : g_d3h;
    const uint4* Ahg = reinterpret_cast<const uint4*>(Ahg16);
    const uint4* Alg = reinterpret_cast<const uint4*>(g_h3l);
    const uint4* Bhg = reinterpret_cast<const uint4*>(g_dW4h);

    const int m0 = blockIdx.y * 128;
    const int n0 = blockIdx.x * 128;
    const int tid = threadIdx.x;
    const int w  = tid >> 5;
    const int wr = w >> 2;
    const int wc = w & 3;
    const int cr  = tid >> 2;
    const int cgc = tid & 3;

    wmma::fragment<wmma::accumulator,16,16,16,float> acc[4][2];
    #pragma unroll
    for (int i=0;i<4;i++)
        #pragma unroll
        for(int j=0;j<2;j++) wmma::fill_fragment(acc[i][j], 0.0f);

    {
        __half* Ah = smb;
        __half* Al = smb + STAGE_H;
        __half* Bh = smb + 2*STAGE_H;
        #pragma unroll
        for (int i=0;i<2;i++) {
            int r = cr + 64*i;
            cpa16(&Ah[r*TS2 + cgc*8], &Ahg[(long)(m0+r)*16 + cgc]);
            cpa16(&Bh[r*TS2 + cgc*8], &Bhg[(n0+r)*16 + cgc]);
            if (path == 0)
                cpa16(&Al[r*TS2 + cgc*8], &Alg[(long)(m0+r)*16 + cgc]);
        }
        cp_commit();
    }

    #pragma unroll 1
    for (int c = 0; c < 4; c++) {
        const int s  = c & 1;
        const int sn = s ^ 1;
        if (c < 3) {
            __half* Ah = smb + sn*3*STAGE_H;
            __half* Al = Ah + STAGE_H;
            __half* Bh = Ah + 2*STAGE_H;
            #pragma unroll
            for (int i=0;i<2;i++) {
                int r = cr + 64*i;
                cpa16(&Ah[r*TS2 + cgc*8], &Ahg[(long)(m0+r)*16 + (c+1)*4 + cgc]);
                cpa16(&Bh[r*TS2 + cgc*8], &Bhg[(n0+r)*16 + (c+1)*4 + cgc]);
                if (path == 0)
                    cpa16(&Al[r*TS2 + cgc*8], &Alg[(long)(m0+r)*16 + (c+1)*4 + cgc]);
            }
            cp_commit();
            cp_wait1();
        } else {
            cp_wait0();
        }
        __syncthreads();
        {
            __half* Ah = smb + s*3*STAGE_H;
            __half* Al = Ah + STAGE_H;
            __half* Bh = Ah + 2*STAGE_H;
            #pragma unroll
            for (int kk = 0; kk < 32; kk += 16) {
                wmma::fragment<wmma::matrix_b,16,16,16,__half,wmma::col_major> bh[2];
                #pragma unroll
                for (int j=0;j<2;j++)
                    wmma::load_matrix_sync(bh[j], &Bh[(wc*32 + j*16)*TS2 + kk], TS2);
                #pragma unroll
                for (int i=0;i<4;i++) {
                    wmma::fragment<wmma::matrix_a,16,16,16,__half,wmma::row_major> ah;
                    wmma::load_matrix_sync(ah, &Ah[(wr*64 + i*16)*TS2 + kk], TS2);
                    #pragma unroll
                    for (int j=0;j<2;j++)
                        wmma::mma_sync(acc[i][j], ah, bh[j], acc[i][j]);
                    if (path == 0) {
                        wmma::fragment<wmma::matrix_a,16,16,16,__half,wmma::row_major> al;
                        wmma::load_matrix_sync(al, &Al[(wr*64 + i*16)*TS2 + kk], TS2);
                        #pragma unroll
                        for (int j=0;j<2;j++)
                            wmma::mma_sync(acc[i][j], al, bh[j], acc[i][j]);
                    }
                }
            }
        }
        __syncthreads();
    }
    // epilogue: per-warp staging, fused bias+store+loss
    float lacc = 0.f;
    float* stage = smf + w * 336;
    #pragma unroll
    for (int i=0;i<4;i++) {
        #pragma unroll
        for (int j=0;j<2;j++) {
            wmma::store_matrix_sync(stage, acc[i][j], 20, wmma::mem_row_major);
            __syncwarp();
            const int mbase = m0 + wr*64 + i*16;
            const int nbase = n0 + wc*32 + j*16;
            #pragma unroll
            for (int q=0;q<8;q++) {
                int e = (tid & 31) + 32*q;
                int r = e >> 4, c = e & 15;
                float v = stage[r*20 + c];
                long m = mbase + r; long n = nbase + c;
                if (path == 0) {
                    v += db4[n];
                    out[XHAT_OFF + m*2048 + n] = v;
                    float df = v - x[m*2048 + n];
                    lacc += df*df;
                } else {
                    float df = v - x_dot[m*2048 + n];
                    lacc += df*df;
                }
            }
            __syncwarp();
        }
    }
    red[tid] = lacc;
    __syncthreads();
    for (int sft = 128; sft > 0; sft >>= 1) {
        if (tid < sft) red[tid] += red[tid + sft];
        __syncthreads();
    }
    if (tid == 0) {
        int idx = blockIdx.y*16 + blockIdx.x;
        if (path == 0) g_part_rec[idx] = red[0];
        else           g_part_sx[idx]  = red[0];
    }
}

// ================= K4: deterministic finalize =================
__global__ void k4_final(const float* __restrict__ coef, float* __restrict__ out) {
    const int w = threadIdx.x >> 5, lane = threadIdx.x & 31;
    float s = 0.f;
    if      (w == 0) { for (int i=lane;i<512;i+=32)  s += g_part_po[i]; }
    else if (w == 1) { for (int i=lane;i<512;i+=32)  s += g_part_tr[i]; }
    else if (w == 2) { for (int i=lane;i<512;i+=32)  s += g_part_sz[i]; }
    else if (w == 3) { for (int i=lane;i<2048;i+=32) s += g_part_rec[i]; }
    else if (w == 4) { for (int i=lane;i<2048;i+=32) s += g_part_sx[i]; }
    else             { for (int i=lane;i<21;i+=32)   s += fabsf(coef[i]); }
    #pragma unroll
    for (int o=16;o>0;o>>=1) s += __shfl_down_sync(0xffffffffu, s, o);
    if (lane == 0) {
        if      (w == 0) out[SCAL_OFF+0] = s / 16384.f;
        else if (w == 1) out[SCAL_OFF+1] = s / 16384.f;
        else if (w == 2) out[SCAL_OFF+4] = s / (16384.f*3.f);
        else if (w == 3) out[SCAL_OFF+2] = s / (16384.f*2048.f);
        else if (w == 4) out[SCAL_OFF+3] = s / (16384.f*2048.f);
        else             out[SCAL_OFF+5] = s / 21.f;
    }
}

// ================= launch =================
extern "C" void kernel_launch(void* const* d_in, const int* in_sizes, int n_in,
                              void* d_out, int out_size) {
    const float* x         = (const float*)d_in[0];
    const float* x_dot     = (const float*)d_in[1];
    const float* treatment = (const float*)d_in[2];
    const float* size_     = (const float*)d_in[3];
    const float* eW1 = (const float*)d_in[4];  const float* eb1 = (const float*)d_in[5];
    const float* eW2 = (const float*)d_in[6];  const float* eb2 = (const float*)d_in[7];
    const float* eW3 = (const float*)d_in[8];  const float* eb3 = (const float*)d_in[9];
    const float* eW4 = (const float*)d_in[10]; const float* eb4 = (const float*)d_in[11];
    const float* dW1 = (const float*)d_in[12]; const float* db1 = (const float*)d_in[13];
    const float* dW2 = (const float*)d_in[14]; const float* db2 = (const float*)d_in[15];
    const float* dW3 = (const float*)d_in[16]; const float* db3 = (const float*)d_in[17];
    const float* dW4 = (const float*)d_in[18]; const float* db4 = (const float*)d_in[19];
    const float* coef = (const float*)d_in[20];
    float* out = (float*)d_out;

    cudaFuncSetAttribute(k1_gemm, cudaFuncAttributeMaxDynamicSharedMemorySize, K1_SMEM);
    cudaFuncSetAttribute(k3_gemm, cudaFuncAttributeMaxDynamicSharedMemorySize, K3_SMEM);
    cudaFuncSetAttribute(k2_chain, cudaFuncAttributeMaxDynamicSharedMemorySize, K2_SMEM);

    k0_prep<<<1024, 256>>>(eW1, dW4);
    k1_gemm<<<dim3(128, 2), 256, K1_SMEM>>>(x, x_dot);
    k2_chain<<<512, 256, K2_SMEM>>>(treatment, size_, eW1, eb1, eW2, eb2, eW3, eb3,
                                    eW4, eb4, dW1, db1, dW2, db2, dW3, db3, coef, out);
    k3_gemm<<<dim3(16, 128, 2), 256, K3_SMEM>>>(db4, x, x_dot, out);
    k4_final<<<1, 192>>>(coef, out);
}